// round 6
// baseline (speedup 1.0000x reference)
#include <cuda_runtime.h>
#include <math.h>

#define BB 32
#define CC 256
#define DD 128
#define NN 1024
#define EPS 1e-5f
#define SCALE 0.08838834764831843f  // 1/sqrt(128)

#define PADK 136   // smem row stride; PADK % 32 == 8 -> conflict-free fragment LDS

// ---------------- scratch (device globals; no allocations allowed) ----------
__device__ float g_q[2][BB * NN * DD];
__device__ float g_k[2][BB * NN * DD];
__device__ float g_v[2][BB * NN * CC];
__device__ float g_o[2][BB * NN * CC];
__device__ float g_red[64 * 2];

// ---------------- tf32 helpers ----------------------------------------------
__device__ __forceinline__ unsigned f2tf(float f) {
    unsigned u;
    asm("cvt.rna.tf32.f32 %0, %1;" : "=r"(u) : "f"(f));
    return u;
}

__device__ __forceinline__ void mma8(float* c, const unsigned* a, const unsigned* b) {
    asm volatile(
        "mma.sync.aligned.m16n8k8.row.col.f32.tf32.tf32.f32 "
        "{%0,%1,%2,%3}, {%4,%5,%6,%7}, {%8,%9}, {%0,%1,%2,%3};"
        : "+f"(c[0]), "+f"(c[1]), "+f"(c[2]), "+f"(c[3])
        : "r"(a[0]), "r"(a[1]), "r"(a[2]), "r"(a[3]), "r"(b[0]), "r"(b[1]));
}

// ---------------- smem tile loaders (128-wide tiles, stride PADK) ------------
__device__ __forceinline__ void ldg_direct(float4 v[2], const float* __restrict__ src,
                                           int ld, int k0, int x0, int t) {
    int row = t >> 4, col = (t & 15) * 4;
    const float* p = src + (size_t)(k0 + row) * ld + x0 + col;
    v[0] = *(const float4*)(p);
    v[1] = *(const float4*)(p + 64);
}
__device__ __forceinline__ void sts_direct(unsigned (*S)[PADK], const float4 v[2], int t) {
    int row = t >> 4, col = (t & 15) * 4;
    uint4 u0 = make_uint4(f2tf(v[0].x), f2tf(v[0].y), f2tf(v[0].z), f2tf(v[0].w));
    uint4 u1 = make_uint4(f2tf(v[1].x), f2tf(v[1].y), f2tf(v[1].z), f2tf(v[1].w));
    *(uint4*)&S[row][col]      = u0;
    *(uint4*)&S[row][col + 64] = u1;
}
__device__ __forceinline__ void ldg_trans(float4 v[2], const float* __restrict__ src,
                                          int ld, int k0, int x0, int t) {
    int x = t >> 1, k4 = (t & 1) * 4;
    const float* p = src + (size_t)(x0 + x) * ld + k0 + k4;
    v[0] = *(const float4*)(p);
    v[1] = *(const float4*)(p + 8);
}
__device__ __forceinline__ void sts_trans(unsigned (*S)[PADK], const float4 v[2], int t) {
    int x = t >> 1, k4 = (t & 1) * 4;
    S[k4 + 0][x] = f2tf(v[0].x); S[k4 + 1][x]  = f2tf(v[0].y);
    S[k4 + 2][x] = f2tf(v[0].z); S[k4 + 3][x]  = f2tf(v[0].w);
    S[k4 + 8][x] = f2tf(v[1].x); S[k4 + 9][x]  = f2tf(v[1].y);
    S[k4 +10][x] = f2tf(v[1].z); S[k4 +11][x]  = f2tf(v[1].w);
}

// ---------------- warp-MMA compute on one 16-K slice pair (GEMM kernels) -----
__device__ __forceinline__ void compute_tile(const unsigned (*As)[PADK],
                                             const unsigned (*Bs)[PADK],
                                             float acc[4][4][4],
                                             int wm, int wn, int lane) {
    const int r = lane >> 2, cq = lane & 3;
#pragma unroll
    for (int kk = 0; kk < 16; kk += 8) {
        unsigned af[4][4], bf[4][2];
#pragma unroll
        for (int mt = 0; mt < 4; mt++) {
            int mb = wm * 64 + mt * 16;
            af[mt][0] = As[kk + cq][mb + r];
            af[mt][1] = As[kk + cq][mb + r + 8];
            af[mt][2] = As[kk + cq + 4][mb + r];
            af[mt][3] = As[kk + cq + 4][mb + r + 8];
        }
#pragma unroll
        for (int nt = 0; nt < 4; nt++) {
            int nb = wn * 32 + nt * 8;
            bf[nt][0] = Bs[kk + cq][nb + r];
            bf[nt][1] = Bs[kk + cq + 4][nb + r];
        }
#pragma unroll
        for (int mt = 0; mt < 4; mt++)
#pragma unroll
            for (int nt = 0; nt < 4; nt++)
                mma8(acc[mt][nt], af[mt], bf[nt]);
    }
}

// =============================================================================
// proj: Y[b,n,d] = sum_c X[b,c,n] * W[d,c]
// =============================================================================
__global__ __launch_bounds__(256, 2)
void proj_kernel(const float* __restrict__ X, const float* __restrict__ W,
                 int dir, int which) {
    float* Y; int Dout;
    if (which == 0)      { Y = g_q[dir]; Dout = DD; }
    else if (which == 1) { Y = g_k[dir]; Dout = DD; }
    else                 { Y = g_v[dir]; Dout = CC; }

    __shared__ unsigned As[2][16][PADK], Bs[2][16][PADK];
    const int b = blockIdx.z, n0 = blockIdx.x * 128, d0 = blockIdx.y * 128;
    const float* Xb = X + (size_t)b * CC * NN;
    float* Yb = Y + (size_t)b * NN * Dout;
    const int t = threadIdx.x, lane = t & 31, w = t >> 5;
    const int wm = w >> 2, wn = w & 3;
    float acc[4][4][4] = {};
    float4 va[2], vb[2];

    ldg_direct(va, Xb, NN, 0, n0, t);
    ldg_trans (vb, W,  CC, 0, d0, t);
    sts_direct(As[0], va, t); sts_trans(Bs[0], vb, t);
    __syncthreads();
    const int NIT = CC / 16;
    for (int it = 0; it < NIT; it++) {
        int buf = it & 1;
        if (it + 1 < NIT) {
            ldg_direct(va, Xb, NN, (it + 1) * 16, n0, t);
            ldg_trans (vb, W,  CC, (it + 1) * 16, d0, t);
        }
        compute_tile(As[buf], Bs[buf], acc, wm, wn, lane);
        if (it + 1 < NIT) {
            sts_direct(As[buf ^ 1], va, t); sts_trans(Bs[buf ^ 1], vb, t);
            __syncthreads();
        }
    }
    const int r = lane >> 2, cq = lane & 3;
#pragma unroll
    for (int mt = 0; mt < 4; mt++) {
        int row = n0 + wm * 64 + mt * 16 + r;
#pragma unroll
        for (int nt = 0; nt < 4; nt++) {
            int col = d0 + wn * 32 + nt * 8 + cq * 2;
            *(float2*)(Yb + (size_t)row * Dout + col) =
                make_float2(acc[mt][nt][0], acc[mt][nt][1]);
            *(float2*)(Yb + (size_t)(row + 8) * Dout + col) =
                make_float2(acc[mt][nt][2], acc[mt][nt][3]);
        }
    }
}

// =============================================================================
// flash attention: per (z = dir*32+b, q-tile of 128 rows):
//   S = scale * Q Kt (online softmax over kv-tiles of 64) ; O = P V -> g_o
// 512 threads = 16 warps in a 4x4 grid.
// smem (floats): Sq[128][136] | Sk[128][72] | Sv[64][264] | Sp[64][136]
//                | m[128] | l[128] | c[128] | red[4][128]
// =============================================================================
#define FL_SQ 0
#define FL_SK 17408
#define FL_SV 26624
#define FL_SP 43520
#define FL_M  52224
#define FL_L  52352
#define FL_C  52480
#define FL_RED 52608
#define FL_WORDS 53120
#define FL_BYTES (FL_WORDS * 4)

__global__ __launch_bounds__(512, 1)
void flash_kernel() {
    extern __shared__ float sm[];
    unsigned* Sq  = (unsigned*)(sm + FL_SQ);
    unsigned* Sk  = (unsigned*)(sm + FL_SK);
    unsigned* Sv  = (unsigned*)(sm + FL_SV);
    float*    Spf = sm + FL_SP;
    unsigned* Spu = (unsigned*)Spf;
    float* sm_m = sm + FL_M;
    float* sm_l = sm + FL_L;
    float* sm_c = sm + FL_C;
    float* red  = sm + FL_RED;

    const int z = blockIdx.y, dir = z >> 5, b = z & 31;
    const int q0 = blockIdx.x * 128;
    const float* Qg = g_q[dir] + (size_t)b * NN * DD + (size_t)q0 * DD;
    const float* Kg = g_k[dir] + (size_t)b * NN * DD;
    const float* Vg = g_v[dir] + (size_t)b * NN * CC;
    float* Og = g_o[dir] + (size_t)b * NN * CC;

    const int t = threadIdx.x, lane = t & 31, w = t >> 5;
    const int wm = w >> 2, wn = w & 3;
    const int r = lane >> 2, cq = lane & 3;

    // ---- load Q tile (persistent): Sq[k][q] = tf32(Q[q0+q, k]) ----
    {
        int q = t >> 2, k0 = (t & 3) * 32;
#pragma unroll
        for (int i = 0; i < 8; i++) {
            float4 v = *(const float4*)(Qg + (size_t)q * DD + k0 + i * 4);
            int k = k0 + i * 4;
            Sq[(k + 0) * PADK + q] = f2tf(v.x);
            Sq[(k + 1) * PADK + q] = f2tf(v.y);
            Sq[(k + 2) * PADK + q] = f2tf(v.z);
            Sq[(k + 3) * PADK + q] = f2tf(v.w);
        }
    }
    if (t < 128) { sm_m[t] = -1e30f; sm_l[t] = 0.f; }

    float oacc[2][8][4] = {};

    for (int kt = 0; kt < NN / 64; kt++) {
        const int m0 = kt * 64;
        __syncthreads();   // previous iteration finished with Sk/Sv/Sp
        // ---- K tile: Sk[k][j] ----
        {
            int j = t & 63, k0 = (t >> 6) * 16;
#pragma unroll
            for (int i = 0; i < 4; i++) {
                float4 v = *(const float4*)(Kg + (size_t)(m0 + j) * DD + k0 + i * 4);
                int k = k0 + i * 4;
                Sk[(k + 0) * 72 + j] = f2tf(v.x);
                Sk[(k + 1) * 72 + j] = f2tf(v.y);
                Sk[(k + 2) * 72 + j] = f2tf(v.z);
                Sk[(k + 3) * 72 + j] = f2tf(v.w);
            }
        }
        // ---- V tile: Sv[m][c] ----
        {
            int c4 = t & 63, mb = t >> 6;
#pragma unroll
            for (int i = 0; i < 8; i++) {
                int m = mb + i * 8;
                float4 v = *(const float4*)(Vg + (size_t)(m0 + m) * CC + c4 * 4);
                unsigned* p = Sv + m * 264 + c4 * 4;
                p[0] = f2tf(v.x); p[1] = f2tf(v.y);
                p[2] = f2tf(v.z); p[3] = f2tf(v.w);
            }
        }
        __syncthreads();

        // ---- S = Q Kt : M=128(q) N=64(j) K=128 ; warp tile 32x16 ----
        float sacc[2][2][4] = {};
#pragma unroll
        for (int kk = 0; kk < DD; kk += 8) {
            unsigned af[2][4], bf[2][2];
#pragma unroll
            for (int mt = 0; mt < 2; mt++) {
                int mb2 = wm * 32 + mt * 16;
                af[mt][0] = Sq[(kk + cq) * PADK + mb2 + r];
                af[mt][1] = Sq[(kk + cq) * PADK + mb2 + r + 8];
                af[mt][2] = Sq[(kk + cq + 4) * PADK + mb2 + r];
                af[mt][3] = Sq[(kk + cq + 4) * PADK + mb2 + r + 8];
            }
#pragma unroll
            for (int nt = 0; nt < 2; nt++) {
                int nb = wn * 16 + nt * 8;
                bf[nt][0] = Sk[(kk + cq) * 72 + nb + r];
                bf[nt][1] = Sk[(kk + cq + 4) * 72 + nb + r];
            }
#pragma unroll
            for (int mt = 0; mt < 2; mt++)
#pragma unroll
                for (int nt = 0; nt < 2; nt++)
                    mma8(sacc[mt][nt], af[mt], bf[nt]);
        }
        // ---- write scaled S to Sp[j][q] (fp32) ----
#pragma unroll
        for (int mt = 0; mt < 2; mt++) {
            int row = wm * 32 + mt * 16 + r;
#pragma unroll
            for (int nt = 0; nt < 2; nt++) {
                int col = wn * 16 + nt * 8 + cq * 2;
                Spf[(col + 0) * PADK + row]     = sacc[mt][nt][0] * SCALE;
                Spf[(col + 1) * PADK + row]     = sacc[mt][nt][1] * SCALE;
                Spf[(col + 0) * PADK + row + 8] = sacc[mt][nt][2] * SCALE;
                Spf[(col + 1) * PADK + row + 8] = sacc[mt][nt][3] * SCALE;
            }
        }
        __syncthreads();

        // ---- online softmax ----
        {
            int tq = t & 127, part = t >> 7;
            float lm = -1e30f;
#pragma unroll
            for (int i = 0; i < 16; i++)
                lm = fmaxf(lm, Spf[(part * 16 + i) * PADK + tq]);
            red[part * 128 + tq] = lm;
        }
        __syncthreads();
        if (t < 128) {
            float mo = sm_m[t];
            float mn = fmaxf(fmaxf(red[t], red[128 + t]),
                             fmaxf(red[256 + t], red[384 + t]));
            mn = fmaxf(mo, mn);
            sm_c[t] = __expf(mo - mn);
            sm_m[t] = mn;
        }
        __syncthreads();
        {
            int tq = t & 127, part = t >> 7;
            float mn = sm_m[tq];
            float s = 0.f;
#pragma unroll
            for (int i = 0; i < 16; i++) {
                int idx = (part * 16 + i) * PADK + tq;
                float e = __expf(Spf[idx] - mn);
                s += e;
                Spu[idx] = f2tf(e);
            }
            red[part * 128 + tq] = s;
        }
        __syncthreads();
        if (t < 128)
            sm_l[t] = sm_l[t] * sm_c[t] + red[t] + red[128 + t]
                      + red[256 + t] + red[384 + t];
        // ---- rescale O accumulator ----
        {
            float c0 = sm_c[wm * 32 + r],      c1 = sm_c[wm * 32 + r + 8];
            float c2 = sm_c[wm * 32 + 16 + r], c3 = sm_c[wm * 32 + 16 + r + 8];
#pragma unroll
            for (int nt = 0; nt < 8; nt++) {
                oacc[0][nt][0] *= c0; oacc[0][nt][1] *= c0;
                oacc[0][nt][2] *= c1; oacc[0][nt][3] *= c1;
                oacc[1][nt][0] *= c2; oacc[1][nt][1] *= c2;
                oacc[1][nt][2] *= c3; oacc[1][nt][3] *= c3;
            }
        }
        // ---- O += P V : M=128(q) N=256(c) K=64(j) ; warp tile 32x64 ----
#pragma unroll
        for (int kk = 0; kk < 64; kk += 8) {
            unsigned af[2][4], bf[8][2];
#pragma unroll
            for (int mt = 0; mt < 2; mt++) {
                int mb2 = wm * 32 + mt * 16;
                af[mt][0] = Spu[(kk + cq) * PADK + mb2 + r];
                af[mt][1] = Spu[(kk + cq) * PADK + mb2 + r + 8];
                af[mt][2] = Spu[(kk + cq + 4) * PADK + mb2 + r];
                af[mt][3] = Spu[(kk + cq + 4) * PADK + mb2 + r + 8];
            }
#pragma unroll
            for (int nt = 0; nt < 8; nt++) {
                int nb = wn * 64 + nt * 8;
                bf[nt][0] = Sv[(kk + cq) * 264 + nb + r];
                bf[nt][1] = Sv[(kk + cq + 4) * 264 + nb + r];
            }
#pragma unroll
            for (int mt = 0; mt < 2; mt++)
#pragma unroll
                for (int nt = 0; nt < 8; nt++)
                    mma8(oacc[mt][nt], af[mt], bf[nt]);
        }
    }
    __syncthreads();   // sm_l final

    // ---- epilogue: O / l -> g_o[b, q0+row, col] ----
    {
        float i0 = 1.f / sm_l[wm * 32 + r];
        float i1 = 1.f / sm_l[wm * 32 + r + 8];
        float i2 = 1.f / sm_l[wm * 32 + 16 + r];
        float i3 = 1.f / sm_l[wm * 32 + 16 + r + 8];
        int row0 = q0 + wm * 32 + r;
#pragma unroll
        for (int nt = 0; nt < 8; nt++) {
            int col = wn * 64 + nt * 8 + cq * 2;
            *(float2*)(Og + (size_t)row0 * CC + col) =
                make_float2(oacc[0][nt][0] * i0, oacc[0][nt][1] * i0);
            *(float2*)(Og + (size_t)(row0 + 8) * CC + col) =
                make_float2(oacc[0][nt][2] * i1, oacc[0][nt][3] * i1);
            *(float2*)(Og + (size_t)(row0 + 16) * CC + col) =
                make_float2(oacc[1][nt][0] * i2, oacc[1][nt][1] * i2);
            *(float2*)(Og + (size_t)(row0 + 24) * CC + col) =
                make_float2(oacc[1][nt][2] * i3, oacc[1][nt][3] * i3);
        }
    }
}

// =============================================================================
// fuse (transposed: M = c, N = n):
// out[c,n] = relu( sum_k fw[c,k]*concat(f,att)[k,n] + fb[c] ) + f[c,n]
// =============================================================================
__global__ __launch_bounds__(256, 2)
void fuse_kernel(const float* __restrict__ fs, const float* __restrict__ fi,
                 const float* __restrict__ fw, const float* __restrict__ fbias,
                 float* __restrict__ outp) {
    __shared__ unsigned As[2][16][PADK], Bs[2][16][PADK];
    const int z = blockIdx.z, dir = z >> 5, b = z & 31;
    const int n0 = blockIdx.x * 128, c0 = blockIdx.y * 128;
    const float* f = dir ? fi : fs;
    const float* fb = f + (size_t)b * CC * NN;
    const float* attb = g_o[dir] + (size_t)b * NN * CC;
    float* ob = outp + (size_t)z * CC * NN;
    const int t = threadIdx.x, lane = t & 31, w = t >> 5;
    const int wm = w >> 2, wn = w & 3;
    float acc[4][4][4] = {};
    float4 va[2], vb4[2];

    ldg_trans (va,  fw, 2 * CC, 0, c0, t);
    ldg_direct(vb4, fb, NN,     0, n0, t);
    sts_trans(As[0], va, t); sts_direct(Bs[0], vb4, t);
    __syncthreads();
    const int NIT = (2 * CC) / 16;
    for (int it = 0; it < NIT; it++) {
        int buf = it & 1;
        bool nxt_direct = false;
        if (it + 1 < NIT) {
            int k0 = (it + 1) * 16;
            ldg_trans(va, fw, 2 * CC, k0, c0, t);
            nxt_direct = (k0 < CC);
            if (nxt_direct) ldg_direct(vb4, fb,   NN, k0,      n0, t);
            else            ldg_trans (vb4, attb, CC, k0 - CC, n0, t);
        }
        compute_tile(As[buf], Bs[buf], acc, wm, wn, lane);
        if (it + 1 < NIT) {
            sts_trans(As[buf ^ 1], va, t);
            if (nxt_direct) sts_direct(Bs[buf ^ 1], vb4, t);
            else            sts_trans (Bs[buf ^ 1], vb4, t);
            __syncthreads();
        }
    }
    const int r = lane >> 2, cq = lane & 3;
#pragma unroll
    for (int mt = 0; mt < 4; mt++) {
        int crow = c0 + wm * 64 + mt * 16 + r;
        float b0 = fbias[crow], b1 = fbias[crow + 8];
#pragma unroll
        for (int nt = 0; nt < 4; nt++) {
            int ncol = n0 + wn * 32 + nt * 8 + cq * 2;
            float2 r0 = *(const float2*)(fb + (size_t)crow * NN + ncol);
            float2 r1 = *(const float2*)(fb + (size_t)(crow + 8) * NN + ncol);
            float2 o0, o1;
            o0.x = fmaxf(acc[mt][nt][0] + b0, 0.f) + r0.x;
            o0.y = fmaxf(acc[mt][nt][1] + b0, 0.f) + r0.y;
            o1.x = fmaxf(acc[mt][nt][2] + b1, 0.f) + r1.x;
            o1.y = fmaxf(acc[mt][nt][3] + b1, 0.f) + r1.y;
            *(float2*)(ob + (size_t)crow * NN + ncol)       = o0;
            *(float2*)(ob + (size_t)(crow + 8) * NN + ncol) = o1;
        }
    }
}

// =============================================================================
// layernorm
// =============================================================================
__global__ void ln_reduce_kernel(const float* __restrict__ outp) {
    __shared__ float rs[8], rss[8];
    const int seg = blockIdx.x;
    const float4* p = (const float4*)(outp + (size_t)seg * CC * NN);
    const int t = threadIdx.x;
    float s = 0.f, ss = 0.f;
    for (int i = t; i < CC * NN / 4; i += 256) {
        float4 v = p[i];
        s  += v.x + v.y + v.z + v.w;
        ss += v.x * v.x + v.y * v.y + v.z * v.z + v.w * v.w;
    }
#pragma unroll
    for (int o = 16; o; o >>= 1) {
        s  += __shfl_xor_sync(0xffffffffu, s, o);
        ss += __shfl_xor_sync(0xffffffffu, ss, o);
    }
    if ((t & 31) == 0) { rs[t >> 5] = s; rss[t >> 5] = ss; }
    __syncthreads();
    if (t == 0) {
        float ts = 0.f, tss = 0.f;
#pragma unroll
        for (int i = 0; i < 8; i++) { ts += rs[i]; tss += rss[i]; }
        float inv_n = 1.0f / (CC * NN);
        float mean = ts * inv_n;
        float var  = tss * inv_n - mean * mean;
        g_red[seg * 2 + 0] = mean;
        g_red[seg * 2 + 1] = rsqrtf(var + EPS);
    }
}

__global__ void ln_norm_kernel(float* __restrict__ outp,
                               const float* __restrict__ lnw_s, const float* __restrict__ lnb_s,
                               const float* __restrict__ lnw_i, const float* __restrict__ lnb_i) {
    const int total4 = 2 * BB * CC * NN / 4;
    for (int i = blockIdx.x * blockDim.x + threadIdx.x; i < total4;
         i += gridDim.x * blockDim.x) {
        int flat = i * 4;
        int seg = flat / (CC * NN);
        int c = (flat >> 10) & (CC - 1);
        float mean = g_red[seg * 2 + 0];
        float rstd = g_red[seg * 2 + 1];
        bool isI = seg >= BB;
        float w  = (isI ? lnw_i : lnw_s)[c];
        float bi = (isI ? lnb_i : lnb_s)[c];
        float4 v = ((float4*)outp)[i];
        v.x = (v.x - mean) * rstd * w + bi;
        v.y = (v.y - mean) * rstd * w + bi;
        v.z = (v.z - mean) * rstd * w + bi;
        v.w = (v.w - mean) * rstd * w + bi;
        ((float4*)outp)[i] = v;
    }
}

// =============================================================================
extern "C" void kernel_launch(void* const* d_in, const int* in_sizes, int n_in,
                              void* d_out, int out_size) {
    const float* fs     = (const float*)d_in[0];
    const float* fi     = (const float*)d_in[1];
    const float* qs_w   = (const float*)d_in[2];
    const float* ks_w   = (const float*)d_in[3];
    const float* vs_w   = (const float*)d_in[4];
    const float* qi_w   = (const float*)d_in[5];
    const float* ki_w   = (const float*)d_in[6];
    const float* vi_w   = (const float*)d_in[7];
    const float* fuse_w = (const float*)d_in[8];
    const float* fuse_b = (const float*)d_in[9];
    const float* ln_s_w = (const float*)d_in[10];
    const float* ln_s_b = (const float*)d_in[11];
    const float* ln_i_w = (const float*)d_in[12];
    const float* ln_i_b = (const float*)d_in[13];
    float* out = (float*)d_out;

    cudaFuncSetAttribute(flash_kernel,
                         cudaFuncAttributeMaxDynamicSharedMemorySize, FL_BYTES);

    dim3 thr(256);
    // dir 0 -> fs_out branch: attn = attend(q=fi@qi_w, k=fs@ks_w, v=fs@vs_w)
    proj_kernel<<<dim3(8, 1, BB), thr>>>(fi, qi_w, 0, 0);
    proj_kernel<<<dim3(8, 1, BB), thr>>>(fs, ks_w, 0, 1);
    proj_kernel<<<dim3(8, 2, BB), thr>>>(fs, vs_w, 0, 2);
    // dir 1 -> fi_out branch: attn = attend(q=fs@qs_w, k=fi@ki_w, v=fi@vi_w)
    proj_kernel<<<dim3(8, 1, BB), thr>>>(fs, qs_w, 1, 0);
    proj_kernel<<<dim3(8, 1, BB), thr>>>(fi, ki_w, 1, 1);
    proj_kernel<<<dim3(8, 2, BB), thr>>>(fi, vi_w, 1, 2);

    flash_kernel<<<dim3(8, 64), 512, FL_BYTES>>>();

    fuse_kernel<<<dim3(8, 2, 64), thr>>>(fs, fi, fuse_w, fuse_b, out);

    ln_reduce_kernel<<<64, 256>>>(out);
    ln_norm_kernel<<<4096, 256>>>(out, ln_s_w, ln_s_b, ln_i_w, ln_i_b);
}

// round 7
// speedup vs baseline: 1.1308x; 1.1308x over previous
#include <cuda_runtime.h>
#include <math.h>

#define BB 32
#define CC 256
#define DD 128
#define NN 1024
#define EPS 1e-5f
#define SCALE 0.08838834764831843f  // 1/sqrt(128)

#define PADK 136   // GEMM smem row stride; %32==8 -> conflict-free fragment LDS

// ---------------- scratch (device globals; no allocations allowed) ----------
__device__ float g_q[2][BB * NN * DD];
__device__ float g_k[2][BB * NN * DD];
__device__ float g_v[2][BB * NN * CC];
__device__ float g_o[2][BB * NN * CC];
__device__ float g_red[64 * 2];

// ---------------- tf32 helpers ----------------------------------------------
__device__ __forceinline__ unsigned f2tf(float f) {
    unsigned u;
    asm("cvt.rna.tf32.f32 %0, %1;" : "=r"(u) : "f"(f));
    return u;
}

__device__ __forceinline__ void mma8(float* c, const unsigned* a, const unsigned* b) {
    asm volatile(
        "mma.sync.aligned.m16n8k8.row.col.f32.tf32.tf32.f32 "
        "{%0,%1,%2,%3}, {%4,%5,%6,%7}, {%8,%9}, {%0,%1,%2,%3};"
        : "+f"(c[0]), "+f"(c[1]), "+f"(c[2]), "+f"(c[3])
        : "r"(a[0]), "r"(a[1]), "r"(a[2]), "r"(a[3]), "r"(b[0]), "r"(b[1]));
}

__device__ __forceinline__ void ldsm4(unsigned* r, const unsigned* p) {
    unsigned addr = (unsigned)__cvta_generic_to_shared(p);
    asm volatile("ldmatrix.sync.aligned.m8n8.x4.shared.b16 {%0,%1,%2,%3}, [%4];"
                 : "=r"(r[0]), "=r"(r[1]), "=r"(r[2]), "=r"(r[3]) : "r"(addr));
}

// ---------------- smem tile loaders for GEMM kernels (stride PADK) -----------
__device__ __forceinline__ void ldg_direct(float4 v[2], const float* __restrict__ src,
                                           int ld, int k0, int x0, int t) {
    int row = t >> 4, col = (t & 15) * 4;
    const float* p = src + (size_t)(k0 + row) * ld + x0 + col;
    v[0] = *(const float4*)(p);
    v[1] = *(const float4*)(p + 64);
}
__device__ __forceinline__ void sts_direct(unsigned (*S)[PADK], const float4 v[2], int t) {
    int row = t >> 4, col = (t & 15) * 4;
    uint4 u0 = make_uint4(f2tf(v[0].x), f2tf(v[0].y), f2tf(v[0].z), f2tf(v[0].w));
    uint4 u1 = make_uint4(f2tf(v[1].x), f2tf(v[1].y), f2tf(v[1].z), f2tf(v[1].w));
    *(uint4*)&S[row][col]      = u0;
    *(uint4*)&S[row][col + 64] = u1;
}
__device__ __forceinline__ void ldg_trans(float4 v[2], const float* __restrict__ src,
                                          int ld, int k0, int x0, int t) {
    int x = t >> 1, k4 = (t & 1) * 4;
    const float* p = src + (size_t)(x0 + x) * ld + k0 + k4;
    v[0] = *(const float4*)(p);
    v[1] = *(const float4*)(p + 8);
}
__device__ __forceinline__ void sts_trans(unsigned (*S)[PADK], const float4 v[2], int t) {
    int x = t >> 1, k4 = (t & 1) * 4;
    S[k4 + 0][x] = f2tf(v[0].x); S[k4 + 1][x]  = f2tf(v[0].y);
    S[k4 + 2][x] = f2tf(v[0].z); S[k4 + 3][x]  = f2tf(v[0].w);
    S[k4 + 8][x] = f2tf(v[1].x); S[k4 + 9][x]  = f2tf(v[1].y);
    S[k4 +10][x] = f2tf(v[1].z); S[k4 +11][x]  = f2tf(v[1].w);
}

__device__ __forceinline__ void compute_tile(const unsigned (*As)[PADK],
                                             const unsigned (*Bs)[PADK],
                                             float acc[4][4][4],
                                             int wm, int wn, int lane) {
    const int r = lane >> 2, cq = lane & 3;
#pragma unroll
    for (int kk = 0; kk < 16; kk += 8) {
        unsigned af[4][4], bf[4][2];
#pragma unroll
        for (int mt = 0; mt < 4; mt++) {
            int mb = wm * 64 + mt * 16;
            af[mt][0] = As[kk + cq][mb + r];
            af[mt][1] = As[kk + cq][mb + r + 8];
            af[mt][2] = As[kk + cq + 4][mb + r];
            af[mt][3] = As[kk + cq + 4][mb + r + 8];
        }
#pragma unroll
        for (int nt = 0; nt < 4; nt++) {
            int nb = wn * 32 + nt * 8;
            bf[nt][0] = Bs[kk + cq][nb + r];
            bf[nt][1] = Bs[kk + cq + 4][nb + r];
        }
#pragma unroll
        for (int mt = 0; mt < 4; mt++)
#pragma unroll
            for (int nt = 0; nt < 4; nt++)
                mma8(acc[mt][nt], af[mt], bf[nt]);
    }
}

// =============================================================================
// proj: Y[b,n,d] = sum_c X[b,c,n] * W[d,c]
// =============================================================================
__global__ __launch_bounds__(256, 2)
void proj_kernel(const float* __restrict__ X, const float* __restrict__ W,
                 int dir, int which) {
    float* Y; int Dout;
    if (which == 0)      { Y = g_q[dir]; Dout = DD; }
    else if (which == 1) { Y = g_k[dir]; Dout = DD; }
    else                 { Y = g_v[dir]; Dout = CC; }

    __shared__ unsigned As[2][16][PADK], Bs[2][16][PADK];
    const int b = blockIdx.z, n0 = blockIdx.x * 128, d0 = blockIdx.y * 128;
    const float* Xb = X + (size_t)b * CC * NN;
    float* Yb = Y + (size_t)b * NN * Dout;
    const int t = threadIdx.x, lane = t & 31, w = t >> 5;
    const int wm = w >> 2, wn = w & 3;
    float acc[4][4][4] = {};
    float4 va[2], vb[2];

    ldg_direct(va, Xb, NN, 0, n0, t);
    ldg_trans (vb, W,  CC, 0, d0, t);
    sts_direct(As[0], va, t); sts_trans(Bs[0], vb, t);
    __syncthreads();
    const int NIT = CC / 16;
    for (int it = 0; it < NIT; it++) {
        int buf = it & 1;
        if (it + 1 < NIT) {
            ldg_direct(va, Xb, NN, (it + 1) * 16, n0, t);
            ldg_trans (vb, W,  CC, (it + 1) * 16, d0, t);
        }
        compute_tile(As[buf], Bs[buf], acc, wm, wn, lane);
        if (it + 1 < NIT) {
            sts_direct(As[buf ^ 1], va, t); sts_trans(Bs[buf ^ 1], vb, t);
            __syncthreads();
        }
    }
    const int r = lane >> 2, cq = lane & 3;
#pragma unroll
    for (int mt = 0; mt < 4; mt++) {
        int row = n0 + wm * 64 + mt * 16 + r;
#pragma unroll
        for (int nt = 0; nt < 4; nt++) {
            int col = d0 + wn * 32 + nt * 8 + cq * 2;
            *(float2*)(Yb + (size_t)row * Dout + col) =
                make_float2(acc[mt][nt][0], acc[mt][nt][1]);
            *(float2*)(Yb + (size_t)(row + 8) * Dout + col) =
                make_float2(acc[mt][nt][2], acc[mt][nt][3]);
        }
    }
}

// =============================================================================
// flash attention v2: ldmatrix fragments + register softmax.
// 512 threads = 16 warps (4x4). q-tile 128, kv-tile 64.
// smem words: Sq[128][132] k-major | Sk[64][132] k-major | Sv[64][264] c-major
//             | Sp[128][68] j-major | m,l,c[128] | rmax[4][128] | rsum[4][128]
// =============================================================================
#define SQS 132
#define SKS 132
#define SVS 264
#define SPS 68
#define FO_Q 0
#define FO_K 16896
#define FO_V 25344
#define FO_P 42240
#define FO_M 50944
#define FO_L 51072
#define FO_C 51200
#define FO_RMAX 51328
#define FO_RSUM 51840
#define FL_WORDS 52352
#define FL_BYTES (FL_WORDS * 4)

__global__ __launch_bounds__(512, 1)
void flash_kernel() {
    extern __shared__ float sm[];
    unsigned* Sq  = (unsigned*)(sm + FO_Q);
    unsigned* Sk  = (unsigned*)(sm + FO_K);
    unsigned* Sv  = (unsigned*)(sm + FO_V);
    unsigned* Spu = (unsigned*)(sm + FO_P);
    float* sm_m = sm + FO_M;
    float* sm_l = sm + FO_L;
    float* sm_c = sm + FO_C;
    float* rmax = sm + FO_RMAX;
    float* rsum = sm + FO_RSUM;

    const int z = blockIdx.y, dir = z >> 5, b = z & 31;
    const int q0 = blockIdx.x * 128;
    const float* Qg = g_q[dir] + (size_t)b * NN * DD + (size_t)q0 * DD;
    const float* Kg = g_k[dir] + (size_t)b * NN * DD;
    const float* Vg = g_v[dir] + (size_t)b * NN * CC;
    float* Og = g_o[dir] + (size_t)b * NN * CC;

    const int t = threadIdx.x, lane = t & 31, w = t >> 5;
    const int wm = w >> 2, wn = w & 3;
    const int r = lane >> 2, cq = lane & 3;

    // ldmatrix per-lane address components
    const int lr15 = lane & 15;
    const int lkhi = (lane >> 4) * 4;                      // 0 or 4
    const int brow = (lane & 7) + ((lane & 16) ? 8 : 0);   // B-frag row
    const int bk   = (lane & 8) ? 4 : 0;                   // B-frag k-half

    // ---- fill Sq[q][k] (k-contiguous, direct copy) ----
    {
        int q = t >> 2, kg = (t & 3) * 4;
#pragma unroll
        for (int i = 0; i < 8; i++) {
            int k = kg + i * 16;
            float4 v = *(const float4*)(Qg + (size_t)q * DD + k);
            unsigned* p = Sq + q * SQS + k;
            p[0] = f2tf(v.x); p[1] = f2tf(v.y); p[2] = f2tf(v.z); p[3] = f2tf(v.w);
        }
    }
    if (t < 128) { sm_m[t] = -1e30f; sm_l[t] = 0.f; }

    float oacc[2][8][4] = {};
    const int R0 = wm * 32 + r;

    for (int kt = 0; kt < NN / 64; kt++) {
        const int m0 = kt * 64;
        __syncthreads();   // prev iter consumed Sk/Sv/Sp; Sq/stats ready
        // ---- fill Sk[j][k] ----
        {
            int j = t >> 3, kg = (t & 7) * 4;
#pragma unroll
            for (int i = 0; i < 4; i++) {
                int k = kg + i * 32;
                float4 v = *(const float4*)(Kg + (size_t)(m0 + j) * DD + k);
                unsigned* p = Sk + j * SKS + k;
                p[0] = f2tf(v.x); p[1] = f2tf(v.y); p[2] = f2tf(v.z); p[3] = f2tf(v.w);
            }
        }
        // ---- fill Sv[j][c] ----
        {
            int c4 = t & 63, mb = t >> 6;
#pragma unroll
            for (int i = 0; i < 8; i++) {
                int m = mb + i * 8;
                float4 v = *(const float4*)(Vg + (size_t)(m0 + m) * CC + c4 * 4);
                unsigned* p = Sv + m * SVS + c4 * 4;
                p[0] = f2tf(v.x); p[1] = f2tf(v.y); p[2] = f2tf(v.z); p[3] = f2tf(v.w);
            }
        }
        __syncthreads();

        // ---- S = Q Kt : warp tile 32(q) x 16(j), ldmatrix fragments ----
        float sacc[2][2][4] = {};
        {
            const unsigned* ap0 = Sq + (wm * 32 + lr15) * SQS + lkhi;
            const unsigned* ap1 = ap0 + 16 * SQS;
            const unsigned* bp  = Sk + (wn * 16 + brow) * SKS + bk;
#pragma unroll
            for (int kk = 0; kk < DD; kk += 8) {
                unsigned a0[4], a1[4], bf[4];
                ldsm4(a0, ap0 + kk);
                ldsm4(a1, ap1 + kk);
                ldsm4(bf, bp + kk);
                mma8(sacc[0][0], a0, bf);
                mma8(sacc[0][1], a0, bf + 2);
                mma8(sacc[1][0], a1, bf);
                mma8(sacc[1][1], a1, bf + 2);
            }
        }

        // ---- register softmax: row-max partials ----
        {
            float pm[4];
#pragma unroll
            for (int mt = 0; mt < 2; mt++)
#pragma unroll
                for (int h = 0; h < 2; h++) {
                    float a = fmaxf(sacc[mt][0][h * 2], sacc[mt][0][h * 2 + 1]);
                    float c = fmaxf(sacc[mt][1][h * 2], sacc[mt][1][h * 2 + 1]);
                    pm[mt * 2 + h] = fmaxf(a, c) * SCALE;
                }
#pragma unroll
            for (int o = 1; o <= 2; o <<= 1)
#pragma unroll
                for (int s = 0; s < 4; s++)
                    pm[s] = fmaxf(pm[s], __shfl_xor_sync(0xffffffffu, pm[s], o));
            if (cq == 0) {
#pragma unroll
                for (int s = 0; s < 4; s++)
                    rmax[wn * 128 + R0 + s * 8] = pm[s];
            }
        }
        __syncthreads();
        if (t < 128) {
            float mo = sm_m[t];
            float mn = fmaxf(fmaxf(rmax[t], rmax[128 + t]),
                             fmaxf(rmax[256 + t], rmax[384 + t]));
            mn = fmaxf(mo, mn);
            sm_c[t] = __expf(mo - mn);
            sm_m[t] = mn;
        }
        __syncthreads();

        // ---- exp in registers, write P (tf32) to Sp[q][j], sum partials ----
        {
            float mnv[4], psum[4] = {0.f, 0.f, 0.f, 0.f};
#pragma unroll
            for (int s = 0; s < 4; s++) mnv[s] = sm_m[R0 + s * 8];
#pragma unroll
            for (int mt = 0; mt < 2; mt++)
#pragma unroll
                for (int h = 0; h < 2; h++) {
                    int s = mt * 2 + h;
                    int row = wm * 32 + mt * 16 + h * 8 + r;
#pragma unroll
                    for (int nt = 0; nt < 2; nt++) {
                        float p0 = __expf(sacc[mt][nt][h * 2]     * SCALE - mnv[s]);
                        float p1 = __expf(sacc[mt][nt][h * 2 + 1] * SCALE - mnv[s]);
                        psum[s] += p0 + p1;
                        int col = wn * 16 + nt * 8 + cq * 2;
                        *(uint2*)&Spu[row * SPS + col] = make_uint2(f2tf(p0), f2tf(p1));
                    }
                }
#pragma unroll
            for (int o = 1; o <= 2; o <<= 1)
#pragma unroll
                for (int s = 0; s < 4; s++)
                    psum[s] += __shfl_xor_sync(0xffffffffu, psum[s], o);
            if (cq == 0) {
#pragma unroll
                for (int s = 0; s < 4; s++)
                    rsum[wn * 128 + R0 + s * 8] = psum[s];
            }
        }
        __syncthreads();   // Sp + rsum ready
        if (t < 128)
            sm_l[t] = sm_l[t] * sm_c[t] + rsum[t] + rsum[128 + t]
                      + rsum[256 + t] + rsum[384 + t];

        // ---- rescale O accumulator ----
        {
            float c0 = sm_c[R0],      c1 = sm_c[R0 + 8];
            float c2 = sm_c[R0 + 16], c3 = sm_c[R0 + 24];
#pragma unroll
            for (int nt = 0; nt < 8; nt++) {
                oacc[0][nt][0] *= c0; oacc[0][nt][1] *= c0;
                oacc[0][nt][2] *= c1; oacc[0][nt][3] *= c1;
                oacc[1][nt][0] *= c2; oacc[1][nt][1] *= c2;
                oacc[1][nt][2] *= c3; oacc[1][nt][3] *= c3;
            }
        }

        // ---- O += P V : warp tile 32(q) x 64(c); A via ldmatrix, B via LDS ----
        {
            const unsigned* pp0 = Spu + (wm * 32 + lr15) * SPS + lkhi;
            const unsigned* pp1 = pp0 + 16 * SPS;
#pragma unroll
            for (int kk = 0; kk < 64; kk += 8) {
                unsigned a0[4], a1[4], bf[8][2];
                ldsm4(a0, pp0 + kk);
                ldsm4(a1, pp1 + kk);
#pragma unroll
                for (int nt = 0; nt < 8; nt++) {
                    int nb = wn * 64 + nt * 8;
                    bf[nt][0] = Sv[(kk + cq) * SVS + nb + r];
                    bf[nt][1] = Sv[(kk + cq + 4) * SVS + nb + r];
                }
#pragma unroll
                for (int nt = 0; nt < 8; nt++) {
                    mma8(oacc[0][nt], a0, bf[nt]);
                    mma8(oacc[1][nt], a1, bf[nt]);
                }
            }
        }
    }
    __syncthreads();   // sm_l final

    // ---- epilogue: O / l -> g_o ----
    {
        float i0 = 1.f / sm_l[R0];
        float i1 = 1.f / sm_l[R0 + 8];
        float i2 = 1.f / sm_l[R0 + 16];
        float i3 = 1.f / sm_l[R0 + 24];
        int row0 = q0 + R0;
#pragma unroll
        for (int nt = 0; nt < 8; nt++) {
            int col = wn * 64 + nt * 8 + cq * 2;
            *(float2*)(Og + (size_t)row0 * CC + col) =
                make_float2(oacc[0][nt][0] * i0, oacc[0][nt][1] * i0);
            *(float2*)(Og + (size_t)(row0 + 8) * CC + col) =
                make_float2(oacc[0][nt][2] * i1, oacc[0][nt][3] * i1);
            *(float2*)(Og + (size_t)(row0 + 16) * CC + col) =
                make_float2(oacc[1][nt][0] * i2, oacc[1][nt][1] * i2);
            *(float2*)(Og + (size_t)(row0 + 24) * CC + col) =
                make_float2(oacc[1][nt][2] * i3, oacc[1][nt][3] * i3);
        }
    }
}

// =============================================================================
// fuse (transposed: M = c, N = n):
// out[c,n] = relu( sum_k fw[c,k]*concat(f,att)[k,n] + fb[c] ) + f[c,n]
// =============================================================================
__global__ __launch_bounds__(256, 2)
void fuse_kernel(const float* __restrict__ fs, const float* __restrict__ fi,
                 const float* __restrict__ fw, const float* __restrict__ fbias,
                 float* __restrict__ outp) {
    __shared__ unsigned As[2][16][PADK], Bs[2][16][PADK];
    const int z = blockIdx.z, dir = z >> 5, b = z & 31;
    const int n0 = blockIdx.x * 128, c0 = blockIdx.y * 128;
    const float* f = dir ? fi : fs;
    const float* fb = f + (size_t)b * CC * NN;
    const float* attb = g_o[dir] + (size_t)b * NN * CC;
    float* ob = outp + (size_t)z * CC * NN;
    const int t = threadIdx.x, lane = t & 31, w = t >> 5;
    const int wm = w >> 2, wn = w & 3;
    float acc[4][4][4] = {};
    float4 va[2], vb4[2];

    ldg_trans (va,  fw, 2 * CC, 0, c0, t);
    ldg_direct(vb4, fb, NN,     0, n0, t);
    sts_trans(As[0], va, t); sts_direct(Bs[0], vb4, t);
    __syncthreads();
    const int NIT = (2 * CC) / 16;
    for (int it = 0; it < NIT; it++) {
        int buf = it & 1;
        bool nxt_direct = false;
        if (it + 1 < NIT) {
            int k0 = (it + 1) * 16;
            ldg_trans(va, fw, 2 * CC, k0, c0, t);
            nxt_direct = (k0 < CC);
            if (nxt_direct) ldg_direct(vb4, fb,   NN, k0,      n0, t);
            else            ldg_trans (vb4, attb, CC, k0 - CC, n0, t);
        }
        compute_tile(As[buf], Bs[buf], acc, wm, wn, lane);
        if (it + 1 < NIT) {
            sts_trans(As[buf ^ 1], va, t);
            if (nxt_direct) sts_direct(Bs[buf ^ 1], vb4, t);
            else            sts_trans (Bs[buf ^ 1], vb4, t);
            __syncthreads();
        }
    }
    const int r = lane >> 2, cq = lane & 3;
#pragma unroll
    for (int mt = 0; mt < 4; mt++) {
        int crow = c0 + wm * 64 + mt * 16 + r;
        float b0 = fbias[crow], b1 = fbias[crow + 8];
#pragma unroll
        for (int nt = 0; nt < 4; nt++) {
            int ncol = n0 + wn * 32 + nt * 8 + cq * 2;
            float2 r0 = *(const float2*)(fb + (size_t)crow * NN + ncol);
            float2 r1 = *(const float2*)(fb + (size_t)(crow + 8) * NN + ncol);
            float2 o0, o1;
            o0.x = fmaxf(acc[mt][nt][0] + b0, 0.f) + r0.x;
            o0.y = fmaxf(acc[mt][nt][1] + b0, 0.f) + r0.y;
            o1.x = fmaxf(acc[mt][nt][2] + b1, 0.f) + r1.x;
            o1.y = fmaxf(acc[mt][nt][3] + b1, 0.f) + r1.y;
            *(float2*)(ob + (size_t)crow * NN + ncol)       = o0;
            *(float2*)(ob + (size_t)(crow + 8) * NN + ncol) = o1;
        }
    }
}

// =============================================================================
// layernorm
// =============================================================================
__global__ void ln_reduce_kernel(const float* __restrict__ outp) {
    __shared__ float rs[8], rss[8];
    const int seg = blockIdx.x;
    const float4* p = (const float4*)(outp + (size_t)seg * CC * NN);
    const int t = threadIdx.x;
    float s = 0.f, ss = 0.f;
    for (int i = t; i < CC * NN / 4; i += 256) {
        float4 v = p[i];
        s  += v.x + v.y + v.z + v.w;
        ss += v.x * v.x + v.y * v.y + v.z * v.z + v.w * v.w;
    }
#pragma unroll
    for (int o = 16; o; o >>= 1) {
        s  += __shfl_xor_sync(0xffffffffu, s, o);
        ss += __shfl_xor_sync(0xffffffffu, ss, o);
    }
    if ((t & 31) == 0) { rs[t >> 5] = s; rss[t >> 5] = ss; }
    __syncthreads();
    if (t == 0) {
        float ts = 0.f, tss = 0.f;
#pragma unroll
        for (int i = 0; i < 8; i++) { ts += rs[i]; tss += rss[i]; }
        float inv_n = 1.0f / (CC * NN);
        float mean = ts * inv_n;
        float var  = tss * inv_n - mean * mean;
        g_red[seg * 2 + 0] = mean;
        g_red[seg * 2 + 1] = rsqrtf(var + EPS);
    }
}

__global__ void ln_norm_kernel(float* __restrict__ outp,
                               const float* __restrict__ lnw_s, const float* __restrict__ lnb_s,
                               const float* __restrict__ lnw_i, const float* __restrict__ lnb_i) {
    const int total4 = 2 * BB * CC * NN / 4;
    for (int i = blockIdx.x * blockDim.x + threadIdx.x; i < total4;
         i += gridDim.x * blockDim.x) {
        int flat = i * 4;
        int seg = flat / (CC * NN);
        int c = (flat >> 10) & (CC - 1);
        float mean = g_red[seg * 2 + 0];
        float rstd = g_red[seg * 2 + 1];
        bool isI = seg >= BB;
        float w  = (isI ? lnw_i : lnw_s)[c];
        float bi = (isI ? lnb_i : lnb_s)[c];
        float4 v = ((float4*)outp)[i];
        v.x = (v.x - mean) * rstd * w + bi;
        v.y = (v.y - mean) * rstd * w + bi;
        v.z = (v.z - mean) * rstd * w + bi;
        v.w = (v.w - mean) * rstd * w + bi;
        ((float4*)outp)[i] = v;
    }
}

// =============================================================================
extern "C" void kernel_launch(void* const* d_in, const int* in_sizes, int n_in,
                              void* d_out, int out_size) {
    const float* fs     = (const float*)d_in[0];
    const float* fi     = (const float*)d_in[1];
    const float* qs_w   = (const float*)d_in[2];
    const float* ks_w   = (const float*)d_in[3];
    const float* vs_w   = (const float*)d_in[4];
    const float* qi_w   = (const float*)d_in[5];
    const float* ki_w   = (const float*)d_in[6];
    const float* vi_w   = (const float*)d_in[7];
    const float* fuse_w = (const float*)d_in[8];
    const float* fuse_b = (const float*)d_in[9];
    const float* ln_s_w = (const float*)d_in[10];
    const float* ln_s_b = (const float*)d_in[11];
    const float* ln_i_w = (const float*)d_in[12];
    const float* ln_i_b = (const float*)d_in[13];
    float* out = (float*)d_out;

    cudaFuncSetAttribute(flash_kernel,
                         cudaFuncAttributeMaxDynamicSharedMemorySize, FL_BYTES);

    dim3 thr(256);
    // dir 0 -> fs_out branch: attn = attend(q=fi@qi_w, k=fs@ks_w, v=fs@vs_w)
    proj_kernel<<<dim3(8, 1, BB), thr>>>(fi, qi_w, 0, 0);
    proj_kernel<<<dim3(8, 1, BB), thr>>>(fs, ks_w, 0, 1);
    proj_kernel<<<dim3(8, 2, BB), thr>>>(fs, vs_w, 0, 2);
    // dir 1 -> fi_out branch: attn = attend(q=fs@qs_w, k=fi@ki_w, v=fi@vi_w)
    proj_kernel<<<dim3(8, 1, BB), thr>>>(fs, qs_w, 1, 0);
    proj_kernel<<<dim3(8, 1, BB), thr>>>(fi, ki_w, 1, 1);
    proj_kernel<<<dim3(8, 2, BB), thr>>>(fi, vi_w, 1, 2);

    flash_kernel<<<dim3(8, 64), 512, FL_BYTES>>>();

    fuse_kernel<<<dim3(8, 2, 64), thr>>>(fs, fi, fuse_w, fuse_b, out);

    ln_reduce_kernel<<<64, 256>>>(out);
    ln_norm_kernel<<<4096, 256>>>(out, ln_s_w, ln_s_b, ln_i_w, ln_i_b);
}

// round 8
// speedup vs baseline: 1.1481x; 1.0153x over previous
#include <cuda_runtime.h>
#include <math.h>

#define BB 32
#define CC 256
#define DD 128
#define NN 1024
#define EPS 1e-5f
#define SCALE 0.08838834764831843f  // 1/sqrt(128)

#define GST 20   // GEMM k-major smem row stride (words); %8==4 -> conflict-free ldsm

// ---------------- scratch (device globals; no allocations allowed) ----------
__device__ float g_q[2][BB * NN * DD];
__device__ float g_k[2][BB * NN * DD];
__device__ float g_v[2][BB * NN * CC];
__device__ float g_o[2][BB * NN * CC];
__device__ float g_red[64 * 2];

// ---------------- helpers ----------------------------------------------------
__device__ __forceinline__ unsigned f2tf(float f) {
    unsigned u;
    asm("cvt.rna.tf32.f32 %0, %1;" : "=r"(u) : "f"(f));
    return u;
}

__device__ __forceinline__ void mma8(float* c, const unsigned* a, const unsigned* b) {
    asm volatile(
        "mma.sync.aligned.m16n8k8.row.col.f32.tf32.tf32.f32 "
        "{%0,%1,%2,%3}, {%4,%5,%6,%7}, {%8,%9}, {%0,%1,%2,%3};"
        : "+f"(c[0]), "+f"(c[1]), "+f"(c[2]), "+f"(c[3])
        : "r"(a[0]), "r"(a[1]), "r"(a[2]), "r"(a[3]), "r"(b[0]), "r"(b[1]));
}

__device__ __forceinline__ void ldsm4(unsigned* r, const unsigned* p) {
    unsigned addr = (unsigned)__cvta_generic_to_shared(p);
    asm volatile("ldmatrix.sync.aligned.m8n8.x4.shared.b16 {%0,%1,%2,%3}, [%4];"
                 : "=r"(r[0]), "=r"(r[1]), "=r"(r[2]), "=r"(r[3]) : "r"(addr));
}

__device__ __forceinline__ void cpa16(void* dst, const void* src) {
    unsigned d = (unsigned)__cvta_generic_to_shared(dst);
    asm volatile("cp.async.ca.shared.global [%0], [%1], 16;" :: "r"(d), "l"(src));
}

// ---------------- GEMM global->reg loaders (coalesced) ------------------------
// kxx layout source: src[k][x] (A transpose case): rows k, contiguous x
__device__ __forceinline__ void ldg_kx(float4 v[2], const float* __restrict__ src,
                                       int ld, int k0, int x0, int t) {
    int row = t >> 4, col = (t & 15) * 4;
    const float* p = src + (size_t)(k0 + row) * ld + x0 + col;
    v[0] = *(const float4*)(p);
    v[1] = *(const float4*)(p + 64);
}
// S[x][k] k-major scatter of ldg_kx data
__device__ __forceinline__ void sts_kx(unsigned* S, const float4 v[2], int t) {
    int k = t >> 4, x = (t & 15) * 4;
    S[(x + 0) * GST + k] = f2tf(v[0].x);
    S[(x + 1) * GST + k] = f2tf(v[0].y);
    S[(x + 2) * GST + k] = f2tf(v[0].z);
    S[(x + 3) * GST + k] = f2tf(v[0].w);
    S[(x + 64) * GST + k] = f2tf(v[1].x);
    S[(x + 65) * GST + k] = f2tf(v[1].y);
    S[(x + 66) * GST + k] = f2tf(v[1].z);
    S[(x + 67) * GST + k] = f2tf(v[1].w);
}
// xk layout source: src[x][k-contig] (direct case)
__device__ __forceinline__ void ldg_xk(float4 v[2], const float* __restrict__ src,
                                       int ld, int k0, int x0, int t) {
    int x = t >> 1, k4 = (t & 1) * 4;
    const float* p = src + (size_t)(x0 + x) * ld + k0 + k4;
    v[0] = *(const float4*)(p);
    v[1] = *(const float4*)(p + 8);
}
__device__ __forceinline__ void sts_xk(unsigned* S, const float4 v[2], int t) {
    int x = t >> 1, k4 = (t & 1) * 4;
    uint4 u0 = make_uint4(f2tf(v[0].x), f2tf(v[0].y), f2tf(v[0].z), f2tf(v[0].w));
    uint4 u1 = make_uint4(f2tf(v[1].x), f2tf(v[1].y), f2tf(v[1].z), f2tf(v[1].w));
    *(uint4*)&S[x * GST + k4]     = u0;
    *(uint4*)&S[x * GST + k4 + 8] = u1;
}

// ---------------- GEMM fragment compute: 128x128 block, BK=16, ldmatrix ------
__device__ __forceinline__ void gemm_frag(const unsigned* As, const unsigned* Bs,
                                          float acc[4][4][4], int wm, int wn, int lane) {
    const int lr15 = lane & 15, lkhi = (lane >> 4) * 4;
    const int brow = (lane & 7) + ((lane & 16) ? 8 : 0);
    const int bk   = (lane & 8) ? 4 : 0;
    const unsigned* bp0 = Bs + (wn * 32 + brow) * GST + bk;
    const unsigned* bp1 = bp0 + 16 * GST;
    const unsigned* ap  = As + (wm * 64 + lr15) * GST + lkhi;
#pragma unroll
    for (int kk = 0; kk < 16; kk += 8) {
        unsigned bf0[4], bf1[4];
        ldsm4(bf0, bp0 + kk);
        ldsm4(bf1, bp1 + kk);
#pragma unroll
        for (int mt = 0; mt < 4; mt++) {
            unsigned af[4];
            ldsm4(af, ap + mt * 16 * GST + kk);
            mma8(acc[mt][0], af, bf0);
            mma8(acc[mt][1], af, bf0 + 2);
            mma8(acc[mt][2], af, bf1);
            mma8(acc[mt][3], af, bf1 + 2);
        }
    }
}

// =============================================================================
// proj_all: all six projections in ONE launch.
// grid (8 n-blocks, 8 slots, 32 b); slot = dir*4 + s;
//   s=0: Q (Dout=128), s=1: K (128), s=2/3: V d-block 0/1 (256)
// Y[b,n,d] = sum_c X[b,c,n] * W[d,c]
// =============================================================================
__global__ __launch_bounds__(256, 2)
void proj_all(const float* __restrict__ fs, const float* __restrict__ fi,
              const float* __restrict__ qs_w, const float* __restrict__ ks_w,
              const float* __restrict__ vs_w, const float* __restrict__ qi_w,
              const float* __restrict__ ki_w, const float* __restrict__ vi_w) {
    const int slot = blockIdx.y, dir = slot >> 2, s = slot & 3;
    const int b = blockIdx.z, n0 = blockIdx.x * 128;
    const float* X; const float* W; float* Y; int Dout, d0;
    if (s == 0)      { X = dir ? fs : fi; W = dir ? qs_w : qi_w; Y = g_q[dir]; Dout = DD; d0 = 0; }
    else if (s == 1) { X = dir ? fi : fs; W = dir ? ki_w : ks_w; Y = g_k[dir]; Dout = DD; d0 = 0; }
    else             { X = dir ? fi : fs; W = dir ? vi_w : vs_w; Y = g_v[dir]; Dout = CC; d0 = (s - 2) * 128; }

    __shared__ unsigned As[2][128 * GST], Bs[2][128 * GST];
    const float* Xb = X + (size_t)b * CC * NN;
    float* Yb = Y + (size_t)b * NN * Dout;
    const int t = threadIdx.x, lane = t & 31, w = t >> 5;
    const int wm = w >> 2, wn = w & 3;
    float acc[4][4][4] = {};
    float4 va[2], vb[2];

    ldg_kx(va, Xb, NN, 0, n0, t);     // A: X[c][n] -> As[n][c]
    ldg_xk(vb, W,  CC, 0, d0, t);     // B: W[d][c] -> Bs[d][c] direct
    sts_kx(As[0], va, t); sts_xk(Bs[0], vb, t);
    __syncthreads();
    const int NIT = CC / 16;
    for (int it = 0; it < NIT; it++) {
        int buf = it & 1;
        if (it + 1 < NIT) {
            ldg_kx(va, Xb, NN, (it + 1) * 16, n0, t);
            ldg_xk(vb, W,  CC, (it + 1) * 16, d0, t);
        }
        gemm_frag(As[buf], Bs[buf], acc, wm, wn, lane);
        if (it + 1 < NIT) {
            sts_kx(As[buf ^ 1], va, t); sts_xk(Bs[buf ^ 1], vb, t);
            __syncthreads();
        }
    }
    const int r = lane >> 2, cq = lane & 3;
#pragma unroll
    for (int mt = 0; mt < 4; mt++) {
        int row = n0 + wm * 64 + mt * 16 + r;
#pragma unroll
        for (int nt = 0; nt < 4; nt++) {
            int col = d0 + wn * 32 + nt * 8 + cq * 2;
            *(float2*)(Yb + (size_t)row * Dout + col) =
                make_float2(acc[mt][nt][0], acc[mt][nt][1]);
            *(float2*)(Yb + (size_t)(row + 8) * Dout + col) =
                make_float2(acc[mt][nt][2], acc[mt][nt][3]);
        }
    }
}

// =============================================================================
// flash attention: ldmatrix + register softmax + cp.async V overlap.
// 512 threads = 16 warps (4x4). q-tile 128, kv-tile 64.
// =============================================================================
#define SQS 132
#define SKS 132
#define SVS 264
#define SPS 68
#define FO_Q 0
#define FO_K 16896
#define FO_V 25344
#define FO_P 42240
#define FO_M 50944
#define FO_L 51072
#define FO_C 51200
#define FO_RMAX 51328
#define FO_RSUM 51840
#define FL_WORDS 52352
#define FL_BYTES (FL_WORDS * 4)

__global__ __launch_bounds__(512, 1)
void flash_kernel() {
    extern __shared__ float sm[];
    unsigned* Sq  = (unsigned*)(sm + FO_Q);
    unsigned* Sk  = (unsigned*)(sm + FO_K);
    unsigned* Sv  = (unsigned*)(sm + FO_V);   // raw fp32 bits (cp.async), cvt at use
    unsigned* Spu = (unsigned*)(sm + FO_P);
    float* sm_m = sm + FO_M;
    float* sm_l = sm + FO_L;
    float* sm_c = sm + FO_C;
    float* rmax = sm + FO_RMAX;
    float* rsum = sm + FO_RSUM;

    const int z = blockIdx.y, dir = z >> 5, b = z & 31;
    const int q0 = blockIdx.x * 128;
    const float* Qg = g_q[dir] + (size_t)b * NN * DD + (size_t)q0 * DD;
    const float* Kg = g_k[dir] + (size_t)b * NN * DD;
    const float* Vg = g_v[dir] + (size_t)b * NN * CC;
    float* Og = g_o[dir] + (size_t)b * NN * CC;

    const int t = threadIdx.x, lane = t & 31, w = t >> 5;
    const int wm = w >> 2, wn = w & 3;
    const int r = lane >> 2, cq = lane & 3;

    const int lr15 = lane & 15;
    const int lkhi = (lane >> 4) * 4;
    const int brow = (lane & 7) + ((lane & 16) ? 8 : 0);
    const int bk   = (lane & 8) ? 4 : 0;

    // ---- fill Sq[q][k] ----
    {
        int q = t >> 2, kg = (t & 3) * 4;
#pragma unroll
        for (int i = 0; i < 8; i++) {
            int k = kg + i * 16;
            float4 v = *(const float4*)(Qg + (size_t)q * DD + k);
            unsigned* p = Sq + q * SQS + k;
            p[0] = f2tf(v.x); p[1] = f2tf(v.y); p[2] = f2tf(v.z); p[3] = f2tf(v.w);
        }
    }
    if (t < 128) { sm_m[t] = -1e30f; sm_l[t] = 0.f; }

    float oacc[2][8][4] = {};
    const int R0 = wm * 32 + r;

    for (int kt = 0; kt < NN / 64; kt++) {
        const int m0 = kt * 64;
        __syncthreads();   // prev iter consumed Sk/Sv/Sp
        // ---- V tile via cp.async (raw fp32) — overlaps QK + softmax ----
        {
            int c4 = t & 63, mb = t >> 6;
#pragma unroll
            for (int i = 0; i < 8; i++) {
                int m = mb + i * 8;
                cpa16(Sv + m * SVS + c4 * 4, Vg + (size_t)(m0 + m) * CC + c4 * 4);
            }
            asm volatile("cp.async.commit_group;" ::: "memory");
        }
        // ---- K tile: Sk[j][k] (needed immediately) ----
        {
            int j = t >> 3, kg = (t & 7) * 4;
#pragma unroll
            for (int i = 0; i < 4; i++) {
                int k = kg + i * 32;
                float4 v = *(const float4*)(Kg + (size_t)(m0 + j) * DD + k);
                unsigned* p = Sk + j * SKS + k;
                p[0] = f2tf(v.x); p[1] = f2tf(v.y); p[2] = f2tf(v.z); p[3] = f2tf(v.w);
            }
        }
        __syncthreads();

        // ---- S = Q Kt : warp tile 32(q) x 16(j) ----
        float sacc[2][2][4] = {};
        {
            const unsigned* ap0 = Sq + (wm * 32 + lr15) * SQS + lkhi;
            const unsigned* ap1 = ap0 + 16 * SQS;
            const unsigned* bp  = Sk + (wn * 16 + brow) * SKS + bk;
#pragma unroll
            for (int kk = 0; kk < DD; kk += 8) {
                unsigned a0[4], a1[4], bf[4];
                ldsm4(a0, ap0 + kk);
                ldsm4(a1, ap1 + kk);
                ldsm4(bf, bp + kk);
                mma8(sacc[0][0], a0, bf);
                mma8(sacc[0][1], a0, bf + 2);
                mma8(sacc[1][0], a1, bf);
                mma8(sacc[1][1], a1, bf + 2);
            }
        }

        // ---- register softmax: row-max partials ----
        {
            float pm[4];
#pragma unroll
            for (int mt = 0; mt < 2; mt++)
#pragma unroll
                for (int h = 0; h < 2; h++) {
                    float a = fmaxf(sacc[mt][0][h * 2], sacc[mt][0][h * 2 + 1]);
                    float c = fmaxf(sacc[mt][1][h * 2], sacc[mt][1][h * 2 + 1]);
                    pm[mt * 2 + h] = fmaxf(a, c) * SCALE;
                }
#pragma unroll
            for (int o = 1; o <= 2; o <<= 1)
#pragma unroll
                for (int s = 0; s < 4; s++)
                    pm[s] = fmaxf(pm[s], __shfl_xor_sync(0xffffffffu, pm[s], o));
            if (cq == 0) {
#pragma unroll
                for (int s = 0; s < 4; s++)
                    rmax[wn * 128 + R0 + s * 8] = pm[s];
            }
        }
        __syncthreads();
        if (t < 128) {
            float mo = sm_m[t];
            float mn = fmaxf(fmaxf(rmax[t], rmax[128 + t]),
                             fmaxf(rmax[256 + t], rmax[384 + t]));
            mn = fmaxf(mo, mn);
            sm_c[t] = __expf(mo - mn);
            sm_m[t] = mn;
        }
        __syncthreads();

        // ---- exp in registers -> Sp[q][j] (tf32), sum partials ----
        {
            float mnv[4], psum[4] = {0.f, 0.f, 0.f, 0.f};
#pragma unroll
            for (int s = 0; s < 4; s++) mnv[s] = sm_m[R0 + s * 8];
#pragma unroll
            for (int mt = 0; mt < 2; mt++)
#pragma unroll
                for (int h = 0; h < 2; h++) {
                    int s = mt * 2 + h;
                    int row = wm * 32 + mt * 16 + h * 8 + r;
#pragma unroll
                    for (int nt = 0; nt < 2; nt++) {
                        float p0 = __expf(sacc[mt][nt][h * 2]     * SCALE - mnv[s]);
                        float p1 = __expf(sacc[mt][nt][h * 2 + 1] * SCALE - mnv[s]);
                        psum[s] += p0 + p1;
                        int col = wn * 16 + nt * 8 + cq * 2;
                        *(uint2*)&Spu[row * SPS + col] = make_uint2(f2tf(p0), f2tf(p1));
                    }
                }
#pragma unroll
            for (int o = 1; o <= 2; o <<= 1)
#pragma unroll
                for (int s = 0; s < 4; s++)
                    psum[s] += __shfl_xor_sync(0xffffffffu, psum[s], o);
            if (cq == 0) {
#pragma unroll
                for (int s = 0; s < 4; s++)
                    rsum[wn * 128 + R0 + s * 8] = psum[s];
            }
        }
        asm volatile("cp.async.wait_group 0;" ::: "memory");
        __syncthreads();   // Sp + rsum + V-tile ready (all threads)
        if (t < 128)
            sm_l[t] = sm_l[t] * sm_c[t] + rsum[t] + rsum[128 + t]
                      + rsum[256 + t] + rsum[384 + t];

        // ---- rescale O accumulator ----
        {
            float c0 = sm_c[R0],      c1 = sm_c[R0 + 8];
            float c2 = sm_c[R0 + 16], c3 = sm_c[R0 + 24];
#pragma unroll
            for (int nt = 0; nt < 8; nt++) {
                oacc[0][nt][0] *= c0; oacc[0][nt][1] *= c0;
                oacc[0][nt][2] *= c1; oacc[0][nt][3] *= c1;
                oacc[1][nt][0] *= c2; oacc[1][nt][1] *= c2;
                oacc[1][nt][2] *= c3; oacc[1][nt][3] *= c3;
            }
        }

        // ---- O += P V : A via ldmatrix, B via LDS + cvt (raw fp32 in Sv) ----
        {
            const unsigned* pp0 = Spu + (wm * 32 + lr15) * SPS + lkhi;
            const unsigned* pp1 = pp0 + 16 * SPS;
#pragma unroll
            for (int kk = 0; kk < 64; kk += 8) {
                unsigned a0[4], a1[4], bf[8][2];
                ldsm4(a0, pp0 + kk);
                ldsm4(a1, pp1 + kk);
#pragma unroll
                for (int nt = 0; nt < 8; nt++) {
                    int nb = wn * 64 + nt * 8;
                    bf[nt][0] = f2tf(__uint_as_float(Sv[(kk + cq) * SVS + nb + r]));
                    bf[nt][1] = f2tf(__uint_as_float(Sv[(kk + cq + 4) * SVS + nb + r]));
                }
#pragma unroll
                for (int nt = 0; nt < 8; nt++) {
                    mma8(oacc[0][nt], a0, bf[nt]);
                    mma8(oacc[1][nt], a1, bf[nt]);
                }
            }
        }
    }
    __syncthreads();   // sm_l final

    // ---- epilogue: O / l -> g_o ----
    {
        float i0 = 1.f / sm_l[R0];
        float i1 = 1.f / sm_l[R0 + 8];
        float i2 = 1.f / sm_l[R0 + 16];
        float i3 = 1.f / sm_l[R0 + 24];
        int row0 = q0 + R0;
#pragma unroll
        for (int nt = 0; nt < 8; nt++) {
            int col = wn * 64 + nt * 8 + cq * 2;
            *(float2*)(Og + (size_t)row0 * CC + col) =
                make_float2(oacc[0][nt][0] * i0, oacc[0][nt][1] * i0);
            *(float2*)(Og + (size_t)(row0 + 8) * CC + col) =
                make_float2(oacc[0][nt][2] * i1, oacc[0][nt][3] * i1);
            *(float2*)(Og + (size_t)(row0 + 16) * CC + col) =
                make_float2(oacc[1][nt][0] * i2, oacc[1][nt][1] * i2);
            *(float2*)(Og + (size_t)(row0 + 24) * CC + col) =
                make_float2(oacc[1][nt][2] * i3, oacc[1][nt][3] * i3);
        }
    }
}

// =============================================================================
// fuse (transposed: M = c, N = n), ldmatrix core:
// out[c,n] = relu( sum_k fw[c,k]*concat(f,att)[k,n] + fb[c] ) + f[c,n]
// =============================================================================
__global__ __launch_bounds__(256, 2)
void fuse_kernel(const float* __restrict__ fs, const float* __restrict__ fi,
                 const float* __restrict__ fw, const float* __restrict__ fbias,
                 float* __restrict__ outp) {
    __shared__ unsigned As[2][128 * GST], Bs[2][128 * GST];
    const int z = blockIdx.z, dir = z >> 5, b = z & 31;
    const int n0 = blockIdx.x * 128, c0 = blockIdx.y * 128;
    const float* f = dir ? fi : fs;
    const float* fb = f + (size_t)b * CC * NN;
    const float* attb = g_o[dir] + (size_t)b * NN * CC;
    float* ob = outp + (size_t)z * CC * NN;
    const int t = threadIdx.x, lane = t & 31, w = t >> 5;
    const int wm = w >> 2, wn = w & 3;
    float acc[4][4][4] = {};
    float4 va[2], vb4[2];

    ldg_xk(va,  fw, 2 * CC, 0, c0, t);   // A: fw[c][k] direct
    ldg_kx(vb4, fb, NN,     0, n0, t);   // B part1: f[k][n] -> transpose
    sts_xk(As[0], va, t); sts_kx(Bs[0], vb4, t);
    __syncthreads();
    const int NIT = (2 * CC) / 16;
    for (int it = 0; it < NIT; it++) {
        int buf = it & 1;
        bool nxt_kx = false;
        if (it + 1 < NIT) {
            int k0 = (it + 1) * 16;
            ldg_xk(va, fw, 2 * CC, k0, c0, t);
            nxt_kx = (k0 < CC);
            if (nxt_kx) ldg_kx(vb4, fb,   NN, k0,      n0, t);
            else        ldg_xk(vb4, attb, CC, k0 - CC, n0, t);
        }
        gemm_frag(As[buf], Bs[buf], acc, wm, wn, lane);
        if (it + 1 < NIT) {
            sts_xk(As[buf ^ 1], va, t);
            if (nxt_kx) sts_kx(Bs[buf ^ 1], vb4, t);
            else        sts_xk(Bs[buf ^ 1], vb4, t);
            __syncthreads();
        }
    }
    const int r = lane >> 2, cq = lane & 3;
#pragma unroll
    for (int mt = 0; mt < 4; mt++) {
        int crow = c0 + wm * 64 + mt * 16 + r;
        float b0 = fbias[crow], b1 = fbias[crow + 8];
#pragma unroll
        for (int nt = 0; nt < 4; nt++) {
            int ncol = n0 + wn * 32 + nt * 8 + cq * 2;
            float2 r0 = *(const float2*)(fb + (size_t)crow * NN + ncol);
            float2 r1 = *(const float2*)(fb + (size_t)(crow + 8) * NN + ncol);
            float2 o0, o1;
            o0.x = fmaxf(acc[mt][nt][0] + b0, 0.f) + r0.x;
            o0.y = fmaxf(acc[mt][nt][1] + b0, 0.f) + r0.y;
            o1.x = fmaxf(acc[mt][nt][2] + b1, 0.f) + r1.x;
            o1.y = fmaxf(acc[mt][nt][3] + b1, 0.f) + r1.y;
            *(float2*)(ob + (size_t)crow * NN + ncol)       = o0;
            *(float2*)(ob + (size_t)(crow + 8) * NN + ncol) = o1;
        }
    }
}

// =============================================================================
// layernorm
// =============================================================================
__global__ void ln_reduce_kernel(const float* __restrict__ outp) {
    __shared__ float rs[8], rss[8];
    const int seg = blockIdx.x;
    const float4* p = (const float4*)(outp + (size_t)seg * CC * NN);
    const int t = threadIdx.x;
    float s = 0.f, ss = 0.f;
    for (int i = t; i < CC * NN / 4; i += 256) {
        float4 v = p[i];
        s  += v.x + v.y + v.z + v.w;
        ss += v.x * v.x + v.y * v.y + v.z * v.z + v.w * v.w;
    }
#pragma unroll
    for (int o = 16; o; o >>= 1) {
        s  += __shfl_xor_sync(0xffffffffu, s, o);
        ss += __shfl_xor_sync(0xffffffffu, ss, o);
    }
    if ((t & 31) == 0) { rs[t >> 5] = s; rss[t >> 5] = ss; }
    __syncthreads();
    if (t == 0) {
        float ts = 0.f, tss = 0.f;
#pragma unroll
        for (int i = 0; i < 8; i++) { ts += rs[i]; tss += rss[i]; }
        float inv_n = 1.0f / (CC * NN);
        float mean = ts * inv_n;
        float var  = tss * inv_n - mean * mean;
        g_red[seg * 2 + 0] = mean;
        g_red[seg * 2 + 1] = rsqrtf(var + EPS);
    }
}

__global__ void ln_norm_kernel(float* __restrict__ outp,
                               const float* __restrict__ lnw_s, const float* __restrict__ lnb_s,
                               const float* __restrict__ lnw_i, const float* __restrict__ lnb_i) {
    const int total4 = 2 * BB * CC * NN / 4;
    for (int i = blockIdx.x * blockDim.x + threadIdx.x; i < total4;
         i += gridDim.x * blockDim.x) {
        int flat = i * 4;
        int seg = flat / (CC * NN);
        int c = (flat >> 10) & (CC - 1);
        float mean = g_red[seg * 2 + 0];
        float rstd = g_red[seg * 2 + 1];
        bool isI = seg >= BB;
        float w  = (isI ? lnw_i : lnw_s)[c];
        float bi = (isI ? lnb_i : lnb_s)[c];
        float4 v = ((float4*)outp)[i];
        v.x = (v.x - mean) * rstd * w + bi;
        v.y = (v.y - mean) * rstd * w + bi;
        v.z = (v.z - mean) * rstd * w + bi;
        v.w = (v.w - mean) * rstd * w + bi;
        ((float4*)outp)[i] = v;
    }
}

// =============================================================================
extern "C" void kernel_launch(void* const* d_in, const int* in_sizes, int n_in,
                              void* d_out, int out_size) {
    const float* fs     = (const float*)d_in[0];
    const float* fi     = (const float*)d_in[1];
    const float* qs_w   = (const float*)d_in[2];
    const float* ks_w   = (const float*)d_in[3];
    const float* vs_w   = (const float*)d_in[4];
    const float* qi_w   = (const float*)d_in[5];
    const float* ki_w   = (const float*)d_in[6];
    const float* vi_w   = (const float*)d_in[7];
    const float* fuse_w = (const float*)d_in[8];
    const float* fuse_b = (const float*)d_in[9];
    const float* ln_s_w = (const float*)d_in[10];
    const float* ln_s_b = (const float*)d_in[11];
    const float* ln_i_w = (const float*)d_in[12];
    const float* ln_i_b = (const float*)d_in[13];
    float* out = (float*)d_out;

    cudaFuncSetAttribute(flash_kernel,
                         cudaFuncAttributeMaxDynamicSharedMemorySize, FL_BYTES);

    proj_all<<<dim3(8, 8, BB), 256>>>(fs, fi, qs_w, ks_w, vs_w, qi_w, ki_w, vi_w);

    flash_kernel<<<dim3(8, 64), 512, FL_BYTES>>>();

    fuse_kernel<<<dim3(8, 2, 64), 256>>>(fs, fi, fuse_w, fuse_b, out);

    ln_reduce_kernel<<<64, 256>>>(out);
    ln_norm_kernel<<<4096, 256>>>(out, ln_s_w, ln_s_b, ln_i_w, ln_i_b);
}

// round 10
// speedup vs baseline: 1.1734x; 1.0220x over previous
#include <cuda_runtime.h>
#include <math.h>

#define BB 32
#define CC 256
#define DD 128
#define NN 1024
#define EPS 1e-5f
#define SCALE 0.08838834764831843f  // 1/sqrt(128)

#define GST 20   // GEMM k-major smem row stride (words); %8==4 -> conflict-free ldsm

// ---------------- scratch (device globals; no allocations allowed) ----------
__device__ float g_q[2][BB * NN * DD];
__device__ float g_k[2][BB * NN * DD];
__device__ float g_v[2][BB * NN * CC];
__device__ float g_o[2][BB * NN * CC];
__device__ float g_part[64][16][2];   // per (seg, block) LN partial (sum, sumsq)
__device__ float g_red[64 * 2];       // per seg: mean, rstd

// ---------------- helpers ----------------------------------------------------
__device__ __forceinline__ unsigned f2tf(float f) {
    unsigned u;
    asm("cvt.rna.tf32.f32 %0, %1;" : "=r"(u) : "f"(f));
    return u;
}

__device__ __forceinline__ void mma8(float* c, const unsigned* a, const unsigned* b) {
    asm volatile(
        "mma.sync.aligned.m16n8k8.row.col.f32.tf32.tf32.f32 "
        "{%0,%1,%2,%3}, {%4,%5,%6,%7}, {%8,%9}, {%0,%1,%2,%3};"
        : "+f"(c[0]), "+f"(c[1]), "+f"(c[2]), "+f"(c[3])
        : "r"(a[0]), "r"(a[1]), "r"(a[2]), "r"(a[3]), "r"(b[0]), "r"(b[1]));
}

__device__ __forceinline__ void ldsm4(unsigned* r, const unsigned* p) {
    unsigned addr = (unsigned)__cvta_generic_to_shared(p);
    asm volatile("ldmatrix.sync.aligned.m8n8.x4.shared.b16 {%0,%1,%2,%3}, [%4];"
                 : "=r"(r[0]), "=r"(r[1]), "=r"(r[2]), "=r"(r[3]) : "r"(addr));
}

__device__ __forceinline__ void ldsm2(unsigned* r, const unsigned* p) {
    unsigned addr = (unsigned)__cvta_generic_to_shared(p);
    asm volatile("ldmatrix.sync.aligned.m8n8.x2.shared.b16 {%0,%1}, [%2];"
                 : "=r"(r[0]), "=r"(r[1]) : "r"(addr));
}

__device__ __forceinline__ void cpa16(void* dst, const void* src) {
    unsigned d = (unsigned)__cvta_generic_to_shared(dst);
    asm volatile("cp.async.ca.shared.global [%0], [%1], 16;" :: "r"(d), "l"(src));
}

// ---------------- GEMM global->reg loaders (coalesced) ------------------------
__device__ __forceinline__ void ldg_kx(float4 v[2], const float* __restrict__ src,
                                       int ld, int k0, int x0, int t) {
    int row = t >> 4, col = (t & 15) * 4;
    const float* p = src + (size_t)(k0 + row) * ld + x0 + col;
    v[0] = *(const float4*)(p);
    v[1] = *(const float4*)(p + 64);
}
__device__ __forceinline__ void sts_kx(unsigned* S, const float4 v[2], int t) {
    int k = t >> 4, x = (t & 15) * 4;
    S[(x + 0) * GST + k] = f2tf(v[0].x);
    S[(x + 1) * GST + k] = f2tf(v[0].y);
    S[(x + 2) * GST + k] = f2tf(v[0].z);
    S[(x + 3) * GST + k] = f2tf(v[0].w);
    S[(x + 64) * GST + k] = f2tf(v[1].x);
    S[(x + 65) * GST + k] = f2tf(v[1].y);
    S[(x + 66) * GST + k] = f2tf(v[1].z);
    S[(x + 67) * GST + k] = f2tf(v[1].w);
}
__device__ __forceinline__ void ldg_xk(float4 v[2], const float* __restrict__ src,
                                       int ld, int k0, int x0, int t) {
    int x = t >> 1, k4 = (t & 1) * 4;
    const float* p = src + (size_t)(x0 + x) * ld + k0 + k4;
    v[0] = *(const float4*)(p);
    v[1] = *(const float4*)(p + 8);
}
__device__ __forceinline__ void sts_xk(unsigned* S, const float4 v[2], int t) {
    int x = t >> 1, k4 = (t & 1) * 4;
    uint4 u0 = make_uint4(f2tf(v[0].x), f2tf(v[0].y), f2tf(v[0].z), f2tf(v[0].w));
    uint4 u1 = make_uint4(f2tf(v[1].x), f2tf(v[1].y), f2tf(v[1].z), f2tf(v[1].w));
    *(uint4*)&S[x * GST + k4]     = u0;
    *(uint4*)&S[x * GST + k4 + 8] = u1;
}

// ---------------- GEMM fragment compute: 128x128 block, BK=16, ldmatrix ------
__device__ __forceinline__ void gemm_frag(const unsigned* As, const unsigned* Bs,
                                          float acc[4][4][4], int wm, int wn, int lane) {
    const int lr15 = lane & 15, lkhi = (lane >> 4) * 4;
    const int brow = (lane & 7) + ((lane & 16) ? 8 : 0);
    const int bk   = (lane & 8) ? 4 : 0;
    const unsigned* bp0 = Bs + (wn * 32 + brow) * GST + bk;
    const unsigned* bp1 = bp0 + 16 * GST;
    const unsigned* ap  = As + (wm * 64 + lr15) * GST + lkhi;
#pragma unroll
    for (int kk = 0; kk < 16; kk += 8) {
        unsigned bf0[4], bf1[4];
        ldsm4(bf0, bp0 + kk);
        ldsm4(bf1, bp1 + kk);
#pragma unroll
        for (int mt = 0; mt < 4; mt++) {
            unsigned af[4];
            ldsm4(af, ap + mt * 16 * GST + kk);
            mma8(acc[mt][0], af, bf0);
            mma8(acc[mt][1], af, bf0 + 2);
            mma8(acc[mt][2], af, bf1);
            mma8(acc[mt][3], af, bf1 + 2);
        }
    }
}

// =============================================================================
// proj_all: all six projections in ONE launch.
// =============================================================================
__global__ __launch_bounds__(256, 2)
void proj_all(const float* __restrict__ fs, const float* __restrict__ fi,
              const float* __restrict__ qs_w, const float* __restrict__ ks_w,
              const float* __restrict__ vs_w, const float* __restrict__ qi_w,
              const float* __restrict__ ki_w, const float* __restrict__ vi_w) {
    const int slot = blockIdx.y, dir = slot >> 2, s = slot & 3;
    const int b = blockIdx.z, n0 = blockIdx.x * 128;
    const float* X; const float* W; float* Y; int Dout, d0;
    if (s == 0)      { X = dir ? fs : fi; W = dir ? qs_w : qi_w; Y = g_q[dir]; Dout = DD; d0 = 0; }
    else if (s == 1) { X = dir ? fi : fs; W = dir ? ki_w : ks_w; Y = g_k[dir]; Dout = DD; d0 = 0; }
    else             { X = dir ? fi : fs; W = dir ? vi_w : vs_w; Y = g_v[dir]; Dout = CC; d0 = (s - 2) * 128; }

    __shared__ unsigned As[2][128 * GST], Bs[2][128 * GST];
    const float* Xb = X + (size_t)b * CC * NN;
    float* Yb = Y + (size_t)b * NN * Dout;
    const int t = threadIdx.x, lane = t & 31, w = t >> 5;
    const int wm = w >> 2, wn = w & 3;
    float acc[4][4][4] = {};
    float4 va[2], vb[2];

    ldg_kx(va, Xb, NN, 0, n0, t);
    ldg_xk(vb, W,  CC, 0, d0, t);
    sts_kx(As[0], va, t); sts_xk(Bs[0], vb, t);
    __syncthreads();
    const int NIT = CC / 16;
    for (int it = 0; it < NIT; it++) {
        int buf = it & 1;
        if (it + 1 < NIT) {
            ldg_kx(va, Xb, NN, (it + 1) * 16, n0, t);
            ldg_xk(vb, W,  CC, (it + 1) * 16, d0, t);
        }
        gemm_frag(As[buf], Bs[buf], acc, wm, wn, lane);
        if (it + 1 < NIT) {
            sts_kx(As[buf ^ 1], va, t); sts_xk(Bs[buf ^ 1], vb, t);
            __syncthreads();
        }
    }
    const int r = lane >> 2, cq = lane & 3;
#pragma unroll
    for (int mt = 0; mt < 4; mt++) {
        int row = n0 + wm * 64 + mt * 16 + r;
#pragma unroll
        for (int nt = 0; nt < 4; nt++) {
            int col = d0 + wn * 32 + nt * 8 + cq * 2;
            *(float2*)(Yb + (size_t)row * Dout + col) =
                make_float2(acc[mt][nt][0], acc[mt][nt][1]);
            *(float2*)(Yb + (size_t)(row + 8) * Dout + col) =
                make_float2(acc[mt][nt][2], acc[mt][nt][3]);
        }
    }
}

// =============================================================================
// flash attention v3: occupancy-2 tiles. 256 threads = 8 warps (2m x 4n).
// q-tile 64, kv-tile 32, 32 kv iterations, 4 barriers/iter.
// smem ~94KB -> 2 blocks/SM.
// =============================================================================
#define SQS 132
#define SKS 132
#define SVS 264
#define SPS 36
#define FO_Q 0
#define FO_K 8448
#define FO_V 12672
#define FO_P 21120
#define FO_M 23424   // sm_m[2][64] double-buffered
#define FO_L 23552
#define FO_RMAX 23616
#define FO_RSUM 23872
#define FL_WORDS 24128
#define FL_BYTES (FL_WORDS * 4)

__global__ __launch_bounds__(256, 2)
void flash_kernel() {
    extern __shared__ float sm[];
    unsigned* Sq  = (unsigned*)(sm + FO_Q);
    unsigned* Sk  = (unsigned*)(sm + FO_K);
    unsigned* Sv  = (unsigned*)(sm + FO_V);   // raw fp32 bits via cp.async
    unsigned* Spu = (unsigned*)(sm + FO_P);
    float* sm_m = sm + FO_M;                  // [2][64]
    float* sm_l = sm + FO_L;
    float* rmax = sm + FO_RMAX;               // [4][64]
    float* rsum = sm + FO_RSUM;               // [4][64]

    const int z = blockIdx.y, dir = z >> 5, b = z & 31;
    const int q0 = blockIdx.x * 64;
    const float* Qg = g_q[dir] + (size_t)b * NN * DD + (size_t)q0 * DD;
    const float* Kg = g_k[dir] + (size_t)b * NN * DD;
    const float* Vg = g_v[dir] + (size_t)b * NN * CC;
    float* Og = g_o[dir] + (size_t)b * NN * CC;

    const int t = threadIdx.x, lane = t & 31, w = t >> 5;
    const int wm = w >> 2, wn = w & 3;           // wm 0..1, wn 0..3
    const int r = lane >> 2, cq = lane & 3;

    const int lr15 = lane & 15;
    const int lkhi = (lane >> 4) * 4;
    const int bj   = lane & 7;                   // B-frag row for ldsm2
    const int bk   = (lane & 8) ? 4 : 0;

    // ---- fill Sq[q][k]: 64 x 128 ----
    {
        int q = t >> 2, kg = (t & 3) * 4;
#pragma unroll
        for (int i = 0; i < 8; i++) {
            int k = kg + i * 16;
            float4 v = *(const float4*)(Qg + (size_t)q * DD + k);
            unsigned* p = Sq + q * SQS + k;
            p[0] = f2tf(v.x); p[1] = f2tf(v.y); p[2] = f2tf(v.z); p[3] = f2tf(v.w);
        }
    }
    if (t < 64) { sm_m[t] = -1e30f; sm_l[t] = 0.f; }

    float oacc[2][8][4] = {};
    const int R0 = wm * 32 + r;
    int cur = 0;

    for (int kt = 0; kt < NN / 32; kt++) {
        const int m0 = kt * 32;
        __syncthreads();   // A: prev PV done with Sk/Sv/Sp; sm_m[nxt] visible
        // ---- V tile (32 x 256) via cp.async — overlaps QK + softmax ----
        {
            int c4 = t & 63, mb = t >> 6;
#pragma unroll
            for (int i = 0; i < 8; i++) {
                int m = mb + i * 4;
                cpa16(Sv + m * SVS + c4 * 4, Vg + (size_t)(m0 + m) * CC + c4 * 4);
            }
            asm volatile("cp.async.commit_group;" ::: "memory");
        }
        // ---- K tile: Sk[j][k] 32 x 128 ----
        {
            int j = t >> 3, kg = (t & 7) * 4;
#pragma unroll
            for (int i = 0; i < 4; i++) {
                int k = kg + i * 32;
                float4 v = *(const float4*)(Kg + (size_t)(m0 + j) * DD + k);
                unsigned* p = Sk + j * SKS + k;
                p[0] = f2tf(v.x); p[1] = f2tf(v.y); p[2] = f2tf(v.z); p[3] = f2tf(v.w);
            }
        }
        __syncthreads();   // B: Sk ready

        // ---- S = Q Kt : warp tile 32(q) x 8(j) ----
        float sacc[2][4] = {};
        {
            const unsigned* ap0 = Sq + (wm * 32 + lr15) * SQS + lkhi;
            const unsigned* ap1 = ap0 + 16 * SQS;
            const unsigned* bp  = Sk + (wn * 8 + bj) * SKS + bk;
#pragma unroll
            for (int kk = 0; kk < DD; kk += 8) {
                unsigned a0[4], a1[4], bf[2];
                ldsm4(a0, ap0 + kk);
                ldsm4(a1, ap1 + kk);
                ldsm2(bf, bp + kk);
                mma8(sacc[0], a0, bf);
                mma8(sacc[1], a1, bf);
            }
        }

        // ---- row-max partials over this warp's 8 j ----
        {
            float pm[4];
#pragma unroll
            for (int s = 0; s < 4; s++) {
                int mt = s >> 1, h = s & 1;
                pm[s] = fmaxf(sacc[mt][h * 2], sacc[mt][h * 2 + 1]) * SCALE;
            }
#pragma unroll
            for (int o = 1; o <= 2; o <<= 1)
#pragma unroll
                for (int s = 0; s < 4; s++)
                    pm[s] = fmaxf(pm[s], __shfl_xor_sync(0xffffffffu, pm[s], o));
            if (cq == 0) {
#pragma unroll
                for (int s = 0; s < 4; s++)
                    rmax[wn * 64 + R0 + s * 8] = pm[s];
            }
        }
        __syncthreads();   // C: rmax ready

        // ---- local stats (no broadcast barrier): each thread for its rows ----
        float mnv[4], cloc[4];
#pragma unroll
        for (int s = 0; s < 4; s++) {
            int row = R0 + s * 8;
            float mo = sm_m[cur * 64 + row];
            float mn = fmaxf(fmaxf(rmax[row], rmax[64 + row]),
                             fmaxf(rmax[128 + row], rmax[192 + row]));
            mn = fmaxf(mo, mn);
            mnv[s] = mn;
            cloc[s] = __expf(mo - mn);
        }
        float cl_t = 0.f, mn_t = 0.f;
        if (t < 64) {
            float mo = sm_m[cur * 64 + t];
            mn_t = fmaxf(fmaxf(rmax[t], rmax[64 + t]),
                         fmaxf(rmax[128 + t], rmax[192 + t]));
            mn_t = fmaxf(mo, mn_t);
            cl_t = __expf(mo - mn_t);
            sm_m[(cur ^ 1) * 64 + t] = mn_t;   // others only read sm_m[cur]
        }

        // ---- exp in registers -> Sp[q][j] tf32; sum partials ----
        {
            float psum[4];
#pragma unroll
            for (int s = 0; s < 4; s++) {
                int mt = s >> 1, h = s & 1;
                int row = wm * 32 + mt * 16 + h * 8 + r;
                float p0 = __expf(sacc[mt][h * 2]     * SCALE - mnv[s]);
                float p1 = __expf(sacc[mt][h * 2 + 1] * SCALE - mnv[s]);
                psum[s] = p0 + p1;
                int col = wn * 8 + cq * 2;
                *(uint2*)&Spu[row * SPS + col] = make_uint2(f2tf(p0), f2tf(p1));
            }
#pragma unroll
            for (int o = 1; o <= 2; o <<= 1)
#pragma unroll
                for (int s = 0; s < 4; s++)
                    psum[s] += __shfl_xor_sync(0xffffffffu, psum[s], o);
            if (cq == 0) {
#pragma unroll
                for (int s = 0; s < 4; s++)
                    rsum[wn * 64 + R0 + s * 8] = psum[s];
            }
        }
        asm volatile("cp.async.wait_group 0;" ::: "memory");
        __syncthreads();   // D: Sp, rsum, Sv ready
        if (t < 64)
            sm_l[t] = sm_l[t] * cl_t + rsum[t] + rsum[64 + t]
                      + rsum[128 + t] + rsum[192 + t];

        // ---- rescale O accumulator ----
#pragma unroll
        for (int nt = 0; nt < 8; nt++) {
            oacc[0][nt][0] *= cloc[0]; oacc[0][nt][1] *= cloc[0];
            oacc[0][nt][2] *= cloc[1]; oacc[0][nt][3] *= cloc[1];
            oacc[1][nt][0] *= cloc[2]; oacc[1][nt][1] *= cloc[2];
            oacc[1][nt][2] *= cloc[3]; oacc[1][nt][3] *= cloc[3];
        }

        // ---- O += P V : warp tile 32(q) x 64(c), K=32 ----
        {
            const unsigned* pp0 = Spu + (wm * 32 + lr15) * SPS + lkhi;
            const unsigned* pp1 = pp0 + 16 * SPS;
#pragma unroll
            for (int kk = 0; kk < 32; kk += 8) {
                unsigned a0[4], a1[4], bf[8][2];
                ldsm4(a0, pp0 + kk);
                ldsm4(a1, pp1 + kk);
#pragma unroll
                for (int nt = 0; nt < 8; nt++) {
                    int nb = wn * 64 + nt * 8;
                    bf[nt][0] = f2tf(__uint_as_float(Sv[(kk + cq) * SVS + nb + r]));
                    bf[nt][1] = f2tf(__uint_as_float(Sv[(kk + cq + 4) * SVS + nb + r]));
                }
#pragma unroll
                for (int nt = 0; nt < 8; nt++) {
                    mma8(oacc[0][nt], a0, bf[nt]);
                    mma8(oacc[1][nt], a1, bf[nt]);
                }
            }
        }
        cur ^= 1;
    }
    __syncthreads();   // sm_l final

    // ---- epilogue: O / l -> g_o ----
    {
        float i0 = 1.f / sm_l[R0];
        float i1 = 1.f / sm_l[R0 + 8];
        float i2 = 1.f / sm_l[R0 + 16];
        float i3 = 1.f / sm_l[R0 + 24];
        int row0 = q0 + R0;
#pragma unroll
        for (int nt = 0; nt < 8; nt++) {
            int col = wn * 64 + nt * 8 + cq * 2;
            *(float2*)(Og + (size_t)row0 * CC + col) =
                make_float2(oacc[0][nt][0] * i0, oacc[0][nt][1] * i0);
            *(float2*)(Og + (size_t)(row0 + 8) * CC + col) =
                make_float2(oacc[0][nt][2] * i1, oacc[0][nt][3] * i1);
            *(float2*)(Og + (size_t)(row0 + 16) * CC + col) =
                make_float2(oacc[1][nt][0] * i2, oacc[1][nt][1] * i2);
            *(float2*)(Og + (size_t)(row0 + 24) * CC + col) =
                make_float2(oacc[1][nt][2] * i3, oacc[1][nt][3] * i3);
        }
    }
}

// =============================================================================
// fuse (transposed: M = c, N = n) + fused LN partial reduction.
// =============================================================================
__global__ __launch_bounds__(256, 2)
void fuse_kernel(const float* __restrict__ fs, const float* __restrict__ fi,
                 const float* __restrict__ fw, const float* __restrict__ fbias,
                 float* __restrict__ outp) {
    __shared__ unsigned As[2][128 * GST], Bs[2][128 * GST];
    __shared__ float redS[8], redSS[8];
    const int z = blockIdx.z, dir = z >> 5, b = z & 31;
    const int n0 = blockIdx.x * 128, c0 = blockIdx.y * 128;
    const float* f = dir ? fi : fs;
    const float* fb = f + (size_t)b * CC * NN;
    const float* attb = g_o[dir] + (size_t)b * NN * CC;
    float* ob = outp + (size_t)z * CC * NN;
    const int t = threadIdx.x, lane = t & 31, w = t >> 5;
    const int wm = w >> 2, wn = w & 3;
    float acc[4][4][4] = {};
    float4 va[2], vb4[2];

    ldg_xk(va,  fw, 2 * CC, 0, c0, t);
    ldg_kx(vb4, fb, NN,     0, n0, t);
    sts_xk(As[0], va, t); sts_kx(Bs[0], vb4, t);
    __syncthreads();
    const int NIT = (2 * CC) / 16;
    for (int it = 0; it < NIT; it++) {
        int buf = it & 1;
        bool nxt_kx = false;
        if (it + 1 < NIT) {
            int k0 = (it + 1) * 16;
            ldg_xk(va, fw, 2 * CC, k0, c0, t);
            nxt_kx = (k0 < CC);
            if (nxt_kx) ldg_kx(vb4, fb,   NN, k0,      n0, t);
            else        ldg_xk(vb4, attb, CC, k0 - CC, n0, t);
        }
        gemm_frag(As[buf], Bs[buf], acc, wm, wn, lane);
        if (it + 1 < NIT) {
            sts_xk(As[buf ^ 1], va, t);
            if (nxt_kx) sts_kx(Bs[buf ^ 1], vb4, t);
            else        sts_xk(Bs[buf ^ 1], vb4, t);
            __syncthreads();
        }
    }
    const int r = lane >> 2, cq = lane & 3;
    float ls = 0.f, lss = 0.f;
#pragma unroll
    for (int mt = 0; mt < 4; mt++) {
        int crow = c0 + wm * 64 + mt * 16 + r;
        float b0 = fbias[crow], b1 = fbias[crow + 8];
#pragma unroll
        for (int nt = 0; nt < 4; nt++) {
            int ncol = n0 + wn * 32 + nt * 8 + cq * 2;
            float2 r0 = *(const float2*)(fb + (size_t)crow * NN + ncol);
            float2 r1 = *(const float2*)(fb + (size_t)(crow + 8) * NN + ncol);
            float2 o0, o1;
            o0.x = fmaxf(acc[mt][nt][0] + b0, 0.f) + r0.x;
            o0.y = fmaxf(acc[mt][nt][1] + b0, 0.f) + r0.y;
            o1.x = fmaxf(acc[mt][nt][2] + b1, 0.f) + r1.x;
            o1.y = fmaxf(acc[mt][nt][3] + b1, 0.f) + r1.y;
            *(float2*)(ob + (size_t)crow * NN + ncol)       = o0;
            *(float2*)(ob + (size_t)(crow + 8) * NN + ncol) = o1;
            ls  += o0.x + o0.y + o1.x + o1.y;
            lss += o0.x * o0.x + o0.y * o0.y + o1.x * o1.x + o1.y * o1.y;
        }
    }
    // block-level LN partial reduction (deterministic: fixed tree)
#pragma unroll
    for (int o = 16; o; o >>= 1) {
        ls  += __shfl_xor_sync(0xffffffffu, ls, o);
        lss += __shfl_xor_sync(0xffffffffu, lss, o);
    }
    if (lane == 0) { redS[w] = ls; redSS[w] = lss; }
    __syncthreads();
    if (t == 0) {
        float s = 0.f, ss = 0.f;
#pragma unroll
        for (int i = 0; i < 8; i++) { s += redS[i]; ss += redSS[i]; }
        int blk = blockIdx.y * 8 + blockIdx.x;   // 16 blocks per segment
        g_part[z][blk][0] = s;
        g_part[z][blk][1] = ss;
    }
}

// =============================================================================
// stats: combine 16 partials per segment (fixed order -> deterministic)
// =============================================================================
__global__ void stats_kernel() {
    int seg = blockIdx.x * 32 + threadIdx.x;
    if (seg < 64) {
        float s = 0.f, ss = 0.f;
#pragma unroll
        for (int i = 0; i < 16; i++) { s += g_part[seg][i][0]; ss += g_part[seg][i][1]; }
        float inv_n = 1.0f / (CC * NN);
        float mean = s * inv_n;
        float var  = ss * inv_n - mean * mean;
        g_red[seg * 2 + 0] = mean;
        g_red[seg * 2 + 1] = rsqrtf(var + EPS);
    }
}

__global__ void ln_norm_kernel(float* __restrict__ outp,
                               const float* __restrict__ lnw_s, const float* __restrict__ lnb_s,
                               const float* __restrict__ lnw_i, const float* __restrict__ lnb_i) {
    const int total4 = 2 * BB * CC * NN / 4;
    for (int i = blockIdx.x * blockDim.x + threadIdx.x; i < total4;
         i += gridDim.x * blockDim.x) {
        int flat = i * 4;
        int seg = flat / (CC * NN);
        int c = (flat >> 10) & (CC - 1);
        float mean = g_red[seg * 2 + 0];
        float rstd = g_red[seg * 2 + 1];
        bool isI = seg >= BB;
        float w  = (isI ? lnw_i : lnw_s)[c];
        float bi = (isI ? lnb_i : lnb_s)[c];
        float4 v = ((float4*)outp)[i];
        v.x = (v.x - mean) * rstd * w + bi;
        v.y = (v.y - mean) * rstd * w + bi;
        v.z = (v.z - mean) * rstd * w + bi;
        v.w = (v.w - mean) * rstd * w + bi;
        ((float4*)outp)[i] = v;
    }
}

// =============================================================================
extern "C" void kernel_launch(void* const* d_in, const int* in_sizes, int n_in,
                              void* d_out, int out_size) {
    const float* fs     = (const float*)d_in[0];
    const float* fi     = (const float*)d_in[1];
    const float* qs_w   = (const float*)d_in[2];
    const float* ks_w   = (const float*)d_in[3];
    const float* vs_w   = (const float*)d_in[4];
    const float* qi_w   = (const float*)d_in[5];
    const float* ki_w   = (const float*)d_in[6];
    const float* vi_w   = (const float*)d_in[7];
    const float* fuse_w = (const float*)d_in[8];
    const float* fuse_b = (const float*)d_in[9];
    const float* ln_s_w = (const float*)d_in[10];
    const float* ln_s_b = (const float*)d_in[11];
    const float* ln_i_w = (const float*)d_in[12];
    const float* ln_i_b = (const float*)d_in[13];
    float* out = (float*)d_out;

    cudaFuncSetAttribute(flash_kernel,
                         cudaFuncAttributeMaxDynamicSharedMemorySize, FL_BYTES);

    proj_all<<<dim3(8, 8, BB), 256>>>(fs, fi, qs_w, ks_w, vs_w, qi_w, ki_w, vi_w);

    flash_kernel<<<dim3(16, 64), 256, FL_BYTES>>>();

    fuse_kernel<<<dim3(8, 2, 64), 256>>>(fs, fi, fuse_w, fuse_b, out);

    stats_kernel<<<2, 32>>>();
    ln_norm_kernel<<<4096, 256>>>(out, ln_s_w, ln_s_b, ln_i_w, ln_i_b);
}

// round 12
// speedup vs baseline: 1.2759x; 1.0873x over previous
#include <cuda_runtime.h>
#include <math.h>

#define BB 32
#define CC 256
#define DD 128
#define NN 1024
#define EPS 1e-5f
#define SCALE 0.08838834764831843f  // 1/sqrt(128)

#define GST 20   // GEMM k-major smem row stride (words); %8==4 -> conflict-free ldsm

// ---------------- scratch (device globals; no allocations allowed) ----------
__device__ float g_q[2][BB * NN * DD];
__device__ float g_k[2][BB * NN * DD];
__device__ float g_v[2][BB * NN * CC];
__device__ float g_o[2][BB * NN * CC];
__device__ float g_part[64][16][2];   // per (seg, block) LN partial (sum, sumsq)

// ---------------- helpers ----------------------------------------------------
__device__ __forceinline__ unsigned f2tf(float f) {
    unsigned u;
    asm("cvt.rna.tf32.f32 %0, %1;" : "=r"(u) : "f"(f));
    return u;
}

__device__ __forceinline__ void mma8(float* c, const unsigned* a, const unsigned* b) {
    asm volatile(
        "mma.sync.aligned.m16n8k8.row.col.f32.tf32.tf32.f32 "
        "{%0,%1,%2,%3}, {%4,%5,%6,%7}, {%8,%9}, {%0,%1,%2,%3};"
        : "+f"(c[0]), "+f"(c[1]), "+f"(c[2]), "+f"(c[3])
        : "r"(a[0]), "r"(a[1]), "r"(a[2]), "r"(a[3]), "r"(b[0]), "r"(b[1]));
}

__device__ __forceinline__ void ldsm4(unsigned* r, const unsigned* p) {
    unsigned addr = (unsigned)__cvta_generic_to_shared(p);
    asm volatile("ldmatrix.sync.aligned.m8n8.x4.shared.b16 {%0,%1,%2,%3}, [%4];"
                 : "=r"(r[0]), "=r"(r[1]), "=r"(r[2]), "=r"(r[3]) : "r"(addr));
}

__device__ __forceinline__ void ldsm2(unsigned* r, const unsigned* p) {
    unsigned addr = (unsigned)__cvta_generic_to_shared(p);
    asm volatile("ldmatrix.sync.aligned.m8n8.x2.shared.b16 {%0,%1}, [%2];"
                 : "=r"(r[0]), "=r"(r[1]) : "r"(addr));
}

__device__ __forceinline__ void cpa16(void* dst, const void* src) {
    unsigned d = (unsigned)__cvta_generic_to_shared(dst);
    asm volatile("cp.async.ca.shared.global [%0], [%1], 16;" :: "r"(d), "l"(src));
}
#define CP_COMMIT() asm volatile("cp.async.commit_group;" ::: "memory")
#define CP_WAIT(n)  asm volatile("cp.async.wait_group %0;" :: "n"(n) : "memory")

// ---------------- GEMM loaders ------------------------------------------------
// transpose path: src[k][x] rows -> regs (coalesced)
__device__ __forceinline__ void ldg_kx(float4 v[2], const float* __restrict__ src,
                                       int ld, int k0, int x0, int t) {
    int row = t >> 4, col = (t & 15) * 4;
    const float* p = src + (size_t)(k0 + row) * ld + x0 + col;
    v[0] = *(const float4*)(p);
    v[1] = *(const float4*)(p + 64);
}
// scatter regs to S[x][k] k-major (raw fp32 bits; mma truncates to tf32)
__device__ __forceinline__ void sts_kx(unsigned* S, const float4 v[2], int t) {
    int k = t >> 4, x = (t & 15) * 4;
    S[(x + 0) * GST + k] = __float_as_uint(v[0].x);
    S[(x + 1) * GST + k] = __float_as_uint(v[0].y);
    S[(x + 2) * GST + k] = __float_as_uint(v[0].z);
    S[(x + 3) * GST + k] = __float_as_uint(v[0].w);
    S[(x + 64) * GST + k] = __float_as_uint(v[1].x);
    S[(x + 65) * GST + k] = __float_as_uint(v[1].y);
    S[(x + 66) * GST + k] = __float_as_uint(v[1].z);
    S[(x + 67) * GST + k] = __float_as_uint(v[1].w);
}
// direct path: src[x][k-contig] -> S[x][k] via cp.async (128 rows x 16 floats)
__device__ __forceinline__ void cpa_xk(unsigned* S, const float* __restrict__ src,
                                       int ld, int k0, int x0, int t) {
    int x = t >> 1, off = (t & 1) * 8;
    const float* p = src + (size_t)(x0 + x) * ld + k0 + off;
    cpa16(S + x * GST + off, p);
    cpa16(S + x * GST + off + 4, p + 4);
}

// ---------------- GEMM fragment compute: 128x128 block, BK=16, ldmatrix ------
__device__ __forceinline__ void gemm_frag(const unsigned* As, const unsigned* Bs,
                                          float acc[4][4][4], int wm, int wn, int lane) {
    const int lr15 = lane & 15, lkhi = (lane >> 4) * 4;
    const int brow = (lane & 7) + ((lane & 16) ? 8 : 0);
    const int bk   = (lane & 8) ? 4 : 0;
    const unsigned* bp0 = Bs + (wn * 32 + brow) * GST + bk;
    const unsigned* bp1 = bp0 + 16 * GST;
    const unsigned* ap  = As + (wm * 64 + lr15) * GST + lkhi;
#pragma unroll
    for (int kk = 0; kk < 16; kk += 8) {
        unsigned bf0[4], bf1[4];
        ldsm4(bf0, bp0 + kk);
        ldsm4(bf1, bp1 + kk);
#pragma unroll
        for (int mt = 0; mt < 4; mt++) {
            unsigned af[4];
            ldsm4(af, ap + mt * 16 * GST + kk);
            mma8(acc[mt][0], af, bf0);
            mma8(acc[mt][1], af, bf0 + 2);
            mma8(acc[mt][2], af, bf1);
            mma8(acc[mt][3], af, bf1 + 2);
        }
    }
}

// =============================================================================
// proj_all: all six projections in ONE launch. Y[b,n,d] = sum_c X[b,c,n] W[d,c]
// A (X) transpose via ldg+sts; B (W) direct via cp.async.
// =============================================================================
__global__ __launch_bounds__(256, 2)
void proj_all(const float* __restrict__ fs, const float* __restrict__ fi,
              const float* __restrict__ qs_w, const float* __restrict__ ks_w,
              const float* __restrict__ vs_w, const float* __restrict__ qi_w,
              const float* __restrict__ ki_w, const float* __restrict__ vi_w) {
    const int slot = blockIdx.y, dir = slot >> 2, s = slot & 3;
    const int b = blockIdx.z, n0 = blockIdx.x * 128;
    const float* X; const float* W; float* Y; int Dout, d0;
    if (s == 0)      { X = dir ? fs : fi; W = dir ? qs_w : qi_w; Y = g_q[dir]; Dout = DD; d0 = 0; }
    else if (s == 1) { X = dir ? fi : fs; W = dir ? ki_w : ks_w; Y = g_k[dir]; Dout = DD; d0 = 0; }
    else             { X = dir ? fi : fs; W = dir ? vi_w : vs_w; Y = g_v[dir]; Dout = CC; d0 = (s - 2) * 128; }

    __shared__ unsigned As[2][128 * GST], Bs[2][128 * GST];
    const float* Xb = X + (size_t)b * CC * NN;
    float* Yb = Y + (size_t)b * NN * Dout;
    const int t = threadIdx.x, lane = t & 31, w = t >> 5;
    const int wm = w >> 2, wn = w & 3;
    float acc[4][4][4] = {};
    float4 va[2];

    cpa_xk(Bs[0], W, CC, 0, d0, t);
    CP_COMMIT();
    ldg_kx(va, Xb, NN, 0, n0, t);
    sts_kx(As[0], va, t);
    CP_WAIT(0);
    __syncthreads();
    const int NIT = CC / 16;
    for (int it = 0; it < NIT; it++) {
        int buf = it & 1;
        if (it + 1 < NIT) {
            cpa_xk(Bs[buf ^ 1], W, CC, (it + 1) * 16, d0, t);
            CP_COMMIT();
            ldg_kx(va, Xb, NN, (it + 1) * 16, n0, t);
        }
        gemm_frag(As[buf], Bs[buf], acc, wm, wn, lane);
        if (it + 1 < NIT) {
            sts_kx(As[buf ^ 1], va, t);
            CP_WAIT(0);
            __syncthreads();
        }
    }
    const int r = lane >> 2, cq = lane & 3;
#pragma unroll
    for (int mt = 0; mt < 4; mt++) {
        int row = n0 + wm * 64 + mt * 16 + r;
#pragma unroll
        for (int nt = 0; nt < 4; nt++) {
            int col = d0 + wn * 32 + nt * 8 + cq * 2;
            *(float2*)(Yb + (size_t)row * Dout + col) =
                make_float2(acc[mt][nt][0], acc[mt][nt][1]);
            *(float2*)(Yb + (size_t)(row + 8) * Dout + col) =
                make_float2(acc[mt][nt][2], acc[mt][nt][3]);
        }
    }
}

// =============================================================================
// flash attention: occ-2, q-tile 64 / kv-tile 32, all fills cp.async.
// 256 threads = 8 warps (2m x 4n). smem ~94KB.
// =============================================================================
#define SQS 132
#define SKS 132
#define SVS 264
#define SPS 36
#define FO_Q 0
#define FO_K 8448
#define FO_V 12672
#define FO_P 21120
#define FO_M 23424   // sm_m[2][64] double-buffered
#define FO_L 23552
#define FO_RMAX 23616
#define FO_RSUM 23872
#define FL_WORDS 24128
#define FL_BYTES (FL_WORDS * 4)

__global__ __launch_bounds__(256, 2)
void flash_kernel() {
    extern __shared__ float sm[];
    unsigned* Sq  = (unsigned*)(sm + FO_Q);   // raw fp32 bits
    unsigned* Sk  = (unsigned*)(sm + FO_K);
    unsigned* Sv  = (unsigned*)(sm + FO_V);
    unsigned* Spu = (unsigned*)(sm + FO_P);
    float* sm_m = sm + FO_M;
    float* sm_l = sm + FO_L;
    float* rmax = sm + FO_RMAX;
    float* rsum = sm + FO_RSUM;

    const int z = blockIdx.y, dir = z >> 5, b = z & 31;
    const int q0 = blockIdx.x * 64;
    const float* Qg = g_q[dir] + (size_t)b * NN * DD + (size_t)q0 * DD;
    const float* Kg = g_k[dir] + (size_t)b * NN * DD;
    const float* Vg = g_v[dir] + (size_t)b * NN * CC;
    float* Og = g_o[dir] + (size_t)b * NN * CC;

    const int t = threadIdx.x, lane = t & 31, w = t >> 5;
    const int wm = w >> 2, wn = w & 3;
    const int r = lane >> 2, cq = lane & 3;

    const int lr15 = lane & 15;
    const int lkhi = (lane >> 4) * 4;
    const int bj   = lane & 7;
    const int bk   = (lane & 8) ? 4 : 0;

    // ---- Q tile 64x128 via cp.async (group 0) ----
    {
        int q = t >> 2;
#pragma unroll
        for (int i = 0; i < 8; i++) {
            int off = ((t & 3) + i * 4) * 4;
            cpa16(Sq + q * SQS + off, Qg + (size_t)q * DD + off);
        }
        CP_COMMIT();
    }
    if (t < 64) { sm_m[t] = -1e30f; sm_l[t] = 0.f; }

    float oacc[2][8][4] = {};
    const int R0 = wm * 32 + r;
    int cur = 0;

    for (int kt = 0; kt < NN / 32; kt++) {
        const int m0 = kt * 32;
        __syncthreads();   // A: prev iter done with Sk/Sv/Sp
        // ---- K tile 32x128 cp.async (committed FIRST) ----
        {
            int j = t >> 3;
#pragma unroll
            for (int i = 0; i < 4; i++) {
                int off = ((t & 7) + i * 8) * 4;
                cpa16(Sk + j * SKS + off, Kg + (size_t)(m0 + j) * DD + off);
            }
            CP_COMMIT();
        }
        // ---- V tile 32x256 cp.async (second group; drains before PV) ----
        {
            int c4 = t & 63, mb = t >> 6;
#pragma unroll
            for (int i = 0; i < 8; i++) {
                int m = mb + i * 4;
                cpa16(Sv + m * SVS + c4 * 4, Vg + (size_t)(m0 + m) * CC + c4 * 4);
            }
            CP_COMMIT();
        }
        CP_WAIT(1);        // Q (first iter) + K done; V may still fly
        __syncthreads();   // B: Sk ready

        // ---- S = Q Kt : warp tile 32(q) x 8(j) ----
        float sacc[2][4] = {};
        {
            const unsigned* ap0 = Sq + (wm * 32 + lr15) * SQS + lkhi;
            const unsigned* ap1 = ap0 + 16 * SQS;
            const unsigned* bp  = Sk + (wn * 8 + bj) * SKS + bk;
#pragma unroll
            for (int kk = 0; kk < DD; kk += 8) {
                unsigned a0[4], a1[4], bf[2];
                ldsm4(a0, ap0 + kk);
                ldsm4(a1, ap1 + kk);
                ldsm2(bf, bp + kk);
                mma8(sacc[0], a0, bf);
                mma8(sacc[1], a1, bf);
            }
        }

        // ---- row-max partials ----
        {
            float pm[4];
#pragma unroll
            for (int s = 0; s < 4; s++) {
                int mt = s >> 1, h = s & 1;
                pm[s] = fmaxf(sacc[mt][h * 2], sacc[mt][h * 2 + 1]) * SCALE;
            }
#pragma unroll
            for (int o = 1; o <= 2; o <<= 1)
#pragma unroll
                for (int s = 0; s < 4; s++)
                    pm[s] = fmaxf(pm[s], __shfl_xor_sync(0xffffffffu, pm[s], o));
            if (cq == 0) {
#pragma unroll
                for (int s = 0; s < 4; s++)
                    rmax[wn * 64 + R0 + s * 8] = pm[s];
            }
        }
        __syncthreads();   // C: rmax ready

        // ---- local stats ----
        float mnv[4], cloc[4];
#pragma unroll
        for (int s = 0; s < 4; s++) {
            int row = R0 + s * 8;
            float mo = sm_m[cur * 64 + row];
            float mn = fmaxf(fmaxf(rmax[row], rmax[64 + row]),
                             fmaxf(rmax[128 + row], rmax[192 + row]));
            mn = fmaxf(mo, mn);
            mnv[s] = mn;
            cloc[s] = __expf(mo - mn);
        }
        float cl_t = 0.f;
        if (t < 64) {
            float mo = sm_m[cur * 64 + t];
            float mn_t = fmaxf(fmaxf(rmax[t], rmax[64 + t]),
                               fmaxf(rmax[128 + t], rmax[192 + t]));
            mn_t = fmaxf(mo, mn_t);
            cl_t = __expf(mo - mn_t);
            sm_m[(cur ^ 1) * 64 + t] = mn_t;
        }

        // ---- exp in registers -> Sp[q][j] tf32; sum partials ----
        {
            float psum[4];
#pragma unroll
            for (int s = 0; s < 4; s++) {
                int mt = s >> 1, h = s & 1;
                int row = wm * 32 + mt * 16 + h * 8 + r;
                float p0 = __expf(sacc[mt][h * 2]     * SCALE - mnv[s]);
                float p1 = __expf(sacc[mt][h * 2 + 1] * SCALE - mnv[s]);
                psum[s] = p0 + p1;
                int col = wn * 8 + cq * 2;
                *(uint2*)&Spu[row * SPS + col] = make_uint2(f2tf(p0), f2tf(p1));
            }
#pragma unroll
            for (int o = 1; o <= 2; o <<= 1)
#pragma unroll
                for (int s = 0; s < 4; s++)
                    psum[s] += __shfl_xor_sync(0xffffffffu, psum[s], o);
            if (cq == 0) {
#pragma unroll
                for (int s = 0; s < 4; s++)
                    rsum[wn * 64 + R0 + s * 8] = psum[s];
            }
        }
        CP_WAIT(0);
        __syncthreads();   // D: Sp, rsum, Sv ready
        if (t < 64)
            sm_l[t] = sm_l[t] * cl_t + rsum[t] + rsum[64 + t]
                      + rsum[128 + t] + rsum[192 + t];

        // ---- rescale O ----
#pragma unroll
        for (int nt = 0; nt < 8; nt++) {
            oacc[0][nt][0] *= cloc[0]; oacc[0][nt][1] *= cloc[0];
            oacc[0][nt][2] *= cloc[1]; oacc[0][nt][3] *= cloc[1];
            oacc[1][nt][0] *= cloc[2]; oacc[1][nt][1] *= cloc[2];
            oacc[1][nt][2] *= cloc[3]; oacc[1][nt][3] *= cloc[3];
        }

        // ---- O += P V : warp tile 32(q) x 64(c), K=32 ----
        {
            const unsigned* pp0 = Spu + (wm * 32 + lr15) * SPS + lkhi;
            const unsigned* pp1 = pp0 + 16 * SPS;
#pragma unroll
            for (int kk = 0; kk < 32; kk += 8) {
                unsigned a0[4], a1[4], bf[8][2];
                ldsm4(a0, pp0 + kk);
                ldsm4(a1, pp1 + kk);
#pragma unroll
                for (int nt = 0; nt < 8; nt++) {
                    int nb = wn * 64 + nt * 8;
                    bf[nt][0] = Sv[(kk + cq) * SVS + nb + r];
                    bf[nt][1] = Sv[(kk + cq + 4) * SVS + nb + r];
                }
#pragma unroll
                for (int nt = 0; nt < 8; nt++) {
                    mma8(oacc[0][nt], a0, bf[nt]);
                    mma8(oacc[1][nt], a1, bf[nt]);
                }
            }
        }
        cur ^= 1;
    }
    __syncthreads();   // sm_l final

    // ---- epilogue: O / l -> g_o ----
    {
        float i0 = 1.f / sm_l[R0];
        float i1 = 1.f / sm_l[R0 + 8];
        float i2 = 1.f / sm_l[R0 + 16];
        float i3 = 1.f / sm_l[R0 + 24];
        int row0 = q0 + R0;
#pragma unroll
        for (int nt = 0; nt < 8; nt++) {
            int col = wn * 64 + nt * 8 + cq * 2;
            *(float2*)(Og + (size_t)row0 * CC + col) =
                make_float2(oacc[0][nt][0] * i0, oacc[0][nt][1] * i0);
            *(float2*)(Og + (size_t)(row0 + 8) * CC + col) =
                make_float2(oacc[0][nt][2] * i1, oacc[0][nt][3] * i1);
            *(float2*)(Og + (size_t)(row0 + 16) * CC + col) =
                make_float2(oacc[1][nt][0] * i2, oacc[1][nt][1] * i2);
            *(float2*)(Og + (size_t)(row0 + 24) * CC + col) =
                make_float2(oacc[1][nt][2] * i3, oacc[1][nt][3] * i3);
        }
    }
}

// =============================================================================
// fuse (transposed: M = c, N = n) + fused LN partial reduction.
// A (fw) + B2 (att) via cp.async; B1 (f) transpose via ldg+sts.
// =============================================================================
__global__ __launch_bounds__(256, 2)
void fuse_kernel(const float* __restrict__ fs, const float* __restrict__ fi,
                 const float* __restrict__ fw, const float* __restrict__ fbias,
                 float* __restrict__ outp) {
    __shared__ unsigned As[2][128 * GST], Bs[2][128 * GST];
    __shared__ float redS[8], redSS[8];
    const int z = blockIdx.z, dir = z >> 5, b = z & 31;
    const int n0 = blockIdx.x * 128, c0 = blockIdx.y * 128;
    const float* f = dir ? fi : fs;
    const float* fb = f + (size_t)b * CC * NN;
    const float* attb = g_o[dir] + (size_t)b * NN * CC;
    float* ob = outp + (size_t)z * CC * NN;
    const int t = threadIdx.x, lane = t & 31, w = t >> 5;
    const int wm = w >> 2, wn = w & 3;
    float acc[4][4][4] = {};
    float4 vb4[2];

    cpa_xk(As[0], fw, 2 * CC, 0, c0, t);
    CP_COMMIT();
    ldg_kx(vb4, fb, NN, 0, n0, t);
    sts_kx(Bs[0], vb4, t);
    CP_WAIT(0);
    __syncthreads();
    const int NIT = (2 * CC) / 16;
    for (int it = 0; it < NIT; it++) {
        int buf = it & 1;
        bool nxt_kx = false;
        if (it + 1 < NIT) {
            int k0 = (it + 1) * 16;
            cpa_xk(As[buf ^ 1], fw, 2 * CC, k0, c0, t);
            nxt_kx = (k0 < CC);
            if (nxt_kx) ldg_kx(vb4, fb, NN, k0, n0, t);
            else        cpa_xk(Bs[buf ^ 1], attb, CC, k0 - CC, n0, t);
            CP_COMMIT();
        }
        gemm_frag(As[buf], Bs[buf], acc, wm, wn, lane);
        if (it + 1 < NIT) {
            if (nxt_kx) sts_kx(Bs[buf ^ 1], vb4, t);
            CP_WAIT(0);
            __syncthreads();
        }
    }
    const int r = lane >> 2, cq = lane & 3;
    float ls = 0.f, lss = 0.f;
#pragma unroll
    for (int mt = 0; mt < 4; mt++) {
        int crow = c0 + wm * 64 + mt * 16 + r;
        float b0 = fbias[crow], b1 = fbias[crow + 8];
#pragma unroll
        for (int nt = 0; nt < 4; nt++) {
            int ncol = n0 + wn * 32 + nt * 8 + cq * 2;
            float2 r0 = *(const float2*)(fb + (size_t)crow * NN + ncol);
            float2 r1 = *(const float2*)(fb + (size_t)(crow + 8) * NN + ncol);
            float2 o0, o1;
            o0.x = fmaxf(acc[mt][nt][0] + b0, 0.f) + r0.x;
            o0.y = fmaxf(acc[mt][nt][1] + b0, 0.f) + r0.y;
            o1.x = fmaxf(acc[mt][nt][2] + b1, 0.f) + r1.x;
            o1.y = fmaxf(acc[mt][nt][3] + b1, 0.f) + r1.y;
            *(float2*)(ob + (size_t)crow * NN + ncol)       = o0;
            *(float2*)(ob + (size_t)(crow + 8) * NN + ncol) = o1;
            ls  += o0.x + o0.y + o1.x + o1.y;
            lss += o0.x * o0.x + o0.y * o0.y + o1.x * o1.x + o1.y * o1.y;
        }
    }
#pragma unroll
    for (int o = 16; o; o >>= 1) {
        ls  += __shfl_xor_sync(0xffffffffu, ls, o);
        lss += __shfl_xor_sync(0xffffffffu, lss, o);
    }
    if (lane == 0) { redS[w] = ls; redSS[w] = lss; }
    __syncthreads();
    if (t == 0) {
        float s = 0.f, ss = 0.f;
#pragma unroll
        for (int i = 0; i < 8; i++) { s += redS[i]; ss += redSS[i]; }
        int blk = blockIdx.y * 8 + blockIdx.x;
        g_part[z][blk][0] = s;
        g_part[z][blk][1] = ss;
    }
}

// =============================================================================
// ln_norm: each block recomputes its segment's stats from g_part (deterministic)
// grid (16 parts, 64 segs)
// =============================================================================
__global__ void ln_norm_kernel(float* __restrict__ outp,
                               const float* __restrict__ lnw_s, const float* __restrict__ lnb_s,
                               const float* __restrict__ lnw_i, const float* __restrict__ lnb_i) {
    const int seg = blockIdx.y, part = blockIdx.x;
    float s = 0.f, ss = 0.f;
#pragma unroll
    for (int i = 0; i < 16; i++) { s += g_part[seg][i][0]; ss += g_part[seg][i][1]; }
    const float inv_n = 1.0f / (CC * NN);
    const float mean = s * inv_n;
    const float rstd = rsqrtf(ss * inv_n - mean * mean + EPS);
    const bool isI = seg >= BB;
    const float* lw = isI ? lnw_i : lnw_s;
    const float* lb = isI ? lnb_i : lnb_s;
    float4* base = (float4*)(outp + (size_t)seg * CC * NN + part * 16384);
    for (int i = threadIdx.x; i < 4096; i += 256) {
        int c = part * 16 + (i >> 8);
        float wv = lw[c], bv = lb[c];
        float4 v = base[i];
        v.x = (v.x - mean) * rstd * wv + bv;
        v.y = (v.y - mean) * rstd * wv + bv;
        v.z = (v.z - mean) * rstd * wv + bv;
        v.w = (v.w - mean) * rstd * wv + bv;
        base[i] = v;
    }
}

// =============================================================================
extern "C" void kernel_launch(void* const* d_in, const int* in_sizes, int n_in,
                              void* d_out, int out_size) {
    const float* fs     = (const float*)d_in[0];
    const float* fi     = (const float*)d_in[1];
    const float* qs_w   = (const float*)d_in[2];
    const float* ks_w   = (const float*)d_in[3];
    const float* vs_w   = (const float*)d_in[4];
    const float* qi_w   = (const float*)d_in[5];
    const float* ki_w   = (const float*)d_in[6];
    const float* vi_w   = (const float*)d_in[7];
    const float* fuse_w = (const float*)d_in[8];
    const float* fuse_b = (const float*)d_in[9];
    const float* ln_s_w = (const float*)d_in[10];
    const float* ln_s_b = (const float*)d_in[11];
    const float* ln_i_w = (const float*)d_in[12];
    const float* ln_i_b = (const float*)d_in[13];
    float* out = (float*)d_out;

    cudaFuncSetAttribute(flash_kernel,
                         cudaFuncAttributeMaxDynamicSharedMemorySize, FL_BYTES);

    proj_all<<<dim3(8, 8, BB), 256>>>(fs, fi, qs_w, ks_w, vs_w, qi_w, ki_w, vi_w);

    flash_kernel<<<dim3(16, 64), 256, FL_BYTES>>>();

    fuse_kernel<<<dim3(8, 2, 64), 256>>>(fs, fi, fuse_w, fuse_b, out);

    ln_norm_kernel<<<dim3(16, 64), 256>>>(out, ln_s_w, ln_s_b, ln_i_w, ln_i_b);
}